// round 1
// baseline (speedup 1.0000x reference)
#include <cuda_runtime.h>
#include <math_constants.h>

// Problem constants
constexpr int B_  = 4;
constexpr int L_  = 2048;
constexpr int D_  = 1024;
constexpr int H_  = 16;
constexpr int HD_ = 64;
constexpr int M_  = B_ * L_;       // 8192 rows
constexpr int QKV_N = 3 * D_;      // 3072

// Scratch (allocation-free requirement -> __device__ globals)
__device__ float g_qkv[(size_t)M_ * QKV_N];   // 96 MB
__device__ float g_att[(size_t)M_ * D_];      // 32 MB

// ----------------------------------------------------------------------------
// SGEMM with bias: C[M,N] = A[M,K] @ W[K,N] + bias[N]
// 128x128 block tile, BK=8, 256 threads, 8x8 per-thread microtile.
// ----------------------------------------------------------------------------
__global__ void __launch_bounds__(256, 2) sgemm_bias_kernel(
    const float* __restrict__ A, const float* __restrict__ W,
    const float* __restrict__ bias, float* __restrict__ C,
    int M, int N, int K)
{
    constexpr int BM = 128, BN = 128, BK = 8, TM = 8, TN = 8;
    __shared__ float As[BK][BM];
    __shared__ float Bs[BK][BN];

    const int tid = threadIdx.x;
    const int tx  = tid & 15;       // 0..15 -> col group
    const int ty  = tid >> 4;       // 0..15 -> row group
    const int row0 = blockIdx.y * BM;
    const int col0 = blockIdx.x * BN;

    float acc[TM][TN];
#pragma unroll
    for (int i = 0; i < TM; i++)
#pragma unroll
        for (int j = 0; j < TN; j++) acc[i][j] = 0.f;

    // load mapping: A tile 128x8 (one float4 per thread along K),
    //               B tile 8x128 (one float4 per thread along N)
    const int a_row = tid >> 1;          // 0..127
    const int a_col = (tid & 1) * 4;     // 0 or 4
    const int b_row = tid >> 5;          // 0..7
    const int b_col = (tid & 31) * 4;    // 0..124

    const float* Ap = A + (size_t)row0 * K;
    const float* Wp = W + col0;

    for (int k0 = 0; k0 < K; k0 += BK) {
        float4 av = *(const float4*)(Ap + (size_t)a_row * K + k0 + a_col);
        As[a_col + 0][a_row] = av.x;
        As[a_col + 1][a_row] = av.y;
        As[a_col + 2][a_row] = av.z;
        As[a_col + 3][a_row] = av.w;
        *(float4*)(&Bs[b_row][b_col]) =
            *(const float4*)(Wp + (size_t)(k0 + b_row) * N + b_col);
        __syncthreads();

#pragma unroll
        for (int kk = 0; kk < BK; kk++) {
            float af[TM], bf[TN];
            *(float4*)&af[0] = *(const float4*)&As[kk][ty * TM];
            *(float4*)&af[4] = *(const float4*)&As[kk][ty * TM + 4];
            *(float4*)&bf[0] = *(const float4*)&Bs[kk][tx * TN];
            *(float4*)&bf[4] = *(const float4*)&Bs[kk][tx * TN + 4];
#pragma unroll
            for (int i = 0; i < TM; i++)
#pragma unroll
                for (int j = 0; j < TN; j++)
                    acc[i][j] += af[i] * bf[j];
        }
        __syncthreads();
    }

#pragma unroll
    for (int i = 0; i < TM; i++) {
        const int r = row0 + ty * TM + i;
#pragma unroll
        for (int j = 0; j < TN; j += 4) {
            const int c = col0 + tx * TN + j;
            float4 v;
            v.x = acc[i][j + 0] + bias[c + 0];
            v.y = acc[i][j + 1] + bias[c + 1];
            v.z = acc[i][j + 2] + bias[c + 2];
            v.w = acc[i][j + 3] + bias[c + 3];
            *(float4*)(C + (size_t)r * N + c) = v;
        }
    }
}

// ----------------------------------------------------------------------------
// Flash attention (fp32, causal). One block per (q_tile=64 rows, head, batch).
// 256 threads as 16x16; each thread owns a 4x4 microtile of the 64x64 tiles.
// Online softmax across key tiles (only kt <= qt visited).
// ----------------------------------------------------------------------------
constexpr int LDQ  = 68;  // pitch for d-major Q/K and natural V tiles (float4-aligned)
constexpr int LDS_ = 65;  // pitch for transposed P tile (odd -> bank-spread)
constexpr int RED_P = 17; // reduction array pitch

constexpr int ATTN_SMEM_FLOATS =
    64 * LDQ      /* Qt  */
  + 64 * LDQ      /* KV (K then V) */
  + 64 * LDS_     /* St (P transposed) */
  + 64 * RED_P    /* red */
  + 64 + 64 + 64; /* mrow, lrow, arow */
constexpr size_t ATTN_SMEM_BYTES = (size_t)ATTN_SMEM_FLOATS * sizeof(float);

__global__ void __launch_bounds__(256) attn_kernel(
    const float* __restrict__ qkv, float* __restrict__ out)
{
    extern __shared__ float smem[];
    float* Qt   = smem;                 // [d][i], pitch LDQ
    float* KV   = Qt + 64 * LDQ;        // K: [d][j] transposed; later V: [k][c]
    float* St   = KV + 64 * LDQ;        // [k][i], pitch LDS_
    float* red  = St + 64 * LDS_;       // [64][RED_P]
    float* mrow = red + 64 * RED_P;     // [64]
    float* lrow = mrow + 64;            // [64]
    float* arow = lrow + 64;            // [64]

    const int qt = blockIdx.x;          // 0 .. L/64-1
    const int h  = blockIdx.y;
    const int b  = blockIdx.z;
    const int tid = threadIdx.x;
    const int tx = tid & 15;
    const int ty = tid >> 4;
    const int lane_r = ty * 4;
    const int lane_c = tx * 4;
    const size_t rowstride = (size_t)QKV_N;

    // ---- load Q tile transposed: Qt[d][i] ----
    const float* qbase = qkv + (size_t)(b * L_ + qt * 64) * rowstride + h * HD_;
#pragma unroll
    for (int u = 0; u < 4; u++) {
        const int i = u * 16 + ty;
        const int d = tx * 4;
        float4 v = *(const float4*)(qbase + (size_t)i * rowstride + d);
        Qt[(d + 0) * LDQ + i] = v.x;
        Qt[(d + 1) * LDQ + i] = v.y;
        Qt[(d + 2) * LDQ + i] = v.z;
        Qt[(d + 3) * LDQ + i] = v.w;
    }
    if (tid < 64) { mrow[tid] = -CUDART_INF_F; lrow[tid] = 0.f; }

    float o[4][4];
#pragma unroll
    for (int r = 0; r < 4; r++)
#pragma unroll
        for (int c = 0; c < 4; c++) o[r][c] = 0.f;

    const float scale = 0.125f;  // 1/sqrt(64)
    __syncthreads();

    for (int kt = 0; kt <= qt; kt++) {
        // ---- load K tile transposed into KV: KV[d][j] ----
        const float* kbase =
            qkv + (size_t)(b * L_ + kt * 64) * rowstride + D_ + h * HD_;
#pragma unroll
        for (int u = 0; u < 4; u++) {
            const int j = u * 16 + ty;
            const int d = tx * 4;
            float4 v = *(const float4*)(kbase + (size_t)j * rowstride + d);
            KV[(d + 0) * LDQ + j] = v.x;
            KV[(d + 1) * LDQ + j] = v.y;
            KV[(d + 2) * LDQ + j] = v.z;
            KV[(d + 3) * LDQ + j] = v.w;
        }
        __syncthreads();

        // ---- S = Q @ K^T (4x4 microtile) ----
        float s[4][4];
#pragma unroll
        for (int r = 0; r < 4; r++)
#pragma unroll
            for (int c = 0; c < 4; c++) s[r][c] = 0.f;

#pragma unroll 8
        for (int d = 0; d < 64; d++) {
            float qv[4], kv[4];
            *(float4*)qv = *(const float4*)&Qt[d * LDQ + lane_r];
            *(float4*)kv = *(const float4*)&KV[d * LDQ + lane_c];
#pragma unroll
            for (int r = 0; r < 4; r++)
#pragma unroll
                for (int c = 0; c < 4; c++)
                    s[r][c] += qv[r] * kv[c];
        }

        // ---- scale + causal mask (only diagonal tile needs masking) ----
        const bool diag = (kt == qt);
#pragma unroll
        for (int r = 0; r < 4; r++)
#pragma unroll
            for (int c = 0; c < 4; c++) {
                float v = s[r][c] * scale;
                if (diag && (lane_c + c > lane_r + r)) v = -CUDART_INF_F;
                s[r][c] = v;
            }

        // ---- per-thread row max -> red ----
#pragma unroll
        for (int r = 0; r < 4; r++) {
            float m = fmaxf(fmaxf(s[r][0], s[r][1]), fmaxf(s[r][2], s[r][3]));
            red[(lane_r + r) * RED_P + tx] = m;
        }
        __syncthreads();   // K reads done, red ready

        // ---- load V tile (natural [k][c]) into KV; tid<64 also reduce max ----
        const float* vbase =
            qkv + (size_t)(b * L_ + kt * 64) * rowstride + 2 * D_ + h * HD_;
#pragma unroll
        for (int u = 0; u < 4; u++) {
            const int k = u * 16 + ty;
            const int c = tx * 4;
            *(float4*)&KV[k * LDQ + c] =
                *(const float4*)(vbase + (size_t)k * rowstride + c);
        }
        if (tid < 64) {
            float m = red[tid * RED_P + 0];
#pragma unroll
            for (int t = 1; t < 16; t++) m = fmaxf(m, red[tid * RED_P + t]);
            const float mo = mrow[tid];
            const float mn = fmaxf(mo, m);
            mrow[tid] = mn;
            arow[tid] = __expf(mo - mn);   // mo = -inf on first tile -> 0
        }
        __syncthreads();   // V, mrow, arow ready

        // ---- P = exp(s - m); write transposed St; partial row sums ----
#pragma unroll
        for (int r = 0; r < 4; r++) {
            const float mn = mrow[lane_r + r];
            float rs = 0.f;
#pragma unroll
            for (int c = 0; c < 4; c++) {
                const float p = __expf(s[r][c] - mn);
                St[(lane_c + c) * LDS_ + lane_r + r] = p;
                rs += p;
            }
            red[(lane_r + r) * RED_P + tx] = rs;
        }
        __syncthreads();   // St + red ready

        if (tid < 64) {
            float sum = 0.f;
#pragma unroll
            for (int t = 0; t < 16; t++) sum += red[tid * RED_P + t];
            lrow[tid] = arow[tid] * lrow[tid] + sum;
        }

        // ---- rescale O, then O += P @ V ----
#pragma unroll
        for (int r = 0; r < 4; r++) {
            const float a = arow[lane_r + r];
#pragma unroll
            for (int c = 0; c < 4; c++) o[r][c] *= a;
        }

#pragma unroll 4
        for (int k = 0; k < 64; k++) {
            float pv[4], vv[4];
#pragma unroll
            for (int r = 0; r < 4; r++) pv[r] = St[k * LDS_ + lane_r + r];
            *(float4*)vv = *(const float4*)&KV[k * LDQ + lane_c];
#pragma unroll
            for (int r = 0; r < 4; r++)
#pragma unroll
                for (int c = 0; c < 4; c++)
                    o[r][c] += pv[r] * vv[c];
        }
        __syncthreads();   // St/V reads done before next iter overwrites
    }

    // ---- finalize: divide by l, write back to [B*L, D] layout ----
#pragma unroll
    for (int r = 0; r < 4; r++) {
        const float inv = 1.0f / lrow[lane_r + r];
        float4 v;
        v.x = o[r][0] * inv;
        v.y = o[r][1] * inv;
        v.z = o[r][2] * inv;
        v.w = o[r][3] * inv;
        *(float4*)(out + (size_t)(b * L_ + qt * 64 + lane_r + r) * D_ +
                   h * HD_ + lane_c) = v;
    }
}

// ----------------------------------------------------------------------------
// Launch
// ----------------------------------------------------------------------------
extern "C" void kernel_launch(void* const* d_in, const int* in_sizes, int n_in,
                              void* d_out, int out_size)
{
    const float* x     = (const float*)d_in[0];
    const float* Wqkv  = (const float*)d_in[1];
    const float* bqkv  = (const float*)d_in[2];
    const float* Wproj = (const float*)d_in[3];
    const float* bproj = (const float*)d_in[4];
    float* out = (float*)d_out;

    float* qkv = nullptr;
    float* att = nullptr;
    cudaGetSymbolAddress((void**)&qkv, g_qkv);
    cudaGetSymbolAddress((void**)&att, g_att);

    static bool attr_set = false;
    if (!attr_set) {
        cudaFuncSetAttribute(attn_kernel,
                             cudaFuncAttributeMaxDynamicSharedMemorySize,
                             (int)ATTN_SMEM_BYTES);
        attr_set = true;
    }

    dim3 blk(256);

    // 1) QKV projection: [8192,1024] @ [1024,3072] + b
    sgemm_bias_kernel<<<dim3(QKV_N / 128, M_ / 128), blk>>>(
        x, Wqkv, bqkv, qkv, M_, QKV_N, D_);

    // 2) causal flash attention
    attn_kernel<<<dim3(L_ / 64, H_, B_), blk, ATTN_SMEM_BYTES>>>(qkv, att);

    // 3) output projection: [8192,1024] @ [1024,1024] + b
    sgemm_bias_kernel<<<dim3(D_ / 128, M_ / 128), blk>>>(
        att, Wproj, bproj, out, M_, D_, D_);
}

// round 3
// speedup vs baseline: 1.4419x; 1.4419x over previous
#include <cuda_runtime.h>
#include <cuda_bf16.h>
#include <math_constants.h>
#include <cstdint>

// Problem constants
constexpr int B_  = 4;
constexpr int L_  = 2048;
constexpr int D_  = 1024;
constexpr int H_  = 16;
constexpr int HD_ = 64;
constexpr int M_  = B_ * L_;       // 8192
constexpr int QKV_N = 3 * D_;      // 3072

// ---------------------------------------------------------------------------
// Scratch (allocation-free -> __device__ globals)
// ---------------------------------------------------------------------------
__device__ float g_qkv[(size_t)M_ * QKV_N];            // 96 MB fp32 qkv
__device__ float g_att[(size_t)M_ * D_];               // 32 MB fp32 attn out
__device__ __nv_bfloat16 g_xhi[(size_t)M_ * D_];
__device__ __nv_bfloat16 g_xlo[(size_t)M_ * D_];
__device__ __nv_bfloat16 g_ahi[(size_t)M_ * D_];
__device__ __nv_bfloat16 g_alo[(size_t)M_ * D_];
__device__ __nv_bfloat16 g_wqh[(size_t)QKV_N * D_];    // Wqkv^T [N,K]
__device__ __nv_bfloat16 g_wql[(size_t)QKV_N * D_];
__device__ __nv_bfloat16 g_wph[(size_t)D_ * D_];       // Wproj^T [N,K]
__device__ __nv_bfloat16 g_wpl[(size_t)D_ * D_];

// ---------------------------------------------------------------------------
// PTX helpers
// ---------------------------------------------------------------------------
__device__ __forceinline__ uint32_t smem_u32(const void* p) {
    uint32_t a;
    asm("{ .reg .u64 t; cvta.to.shared.u64 t, %1; cvt.u32.u64 %0, t; }"
        : "=r"(a) : "l"(p));
    return a;
}
__device__ __forceinline__ void cpasync16(uint32_t saddr, const void* g) {
    asm volatile("cp.async.cg.shared.global [%0], [%1], 16;" :: "r"(saddr), "l"(g));
}
#define CP_COMMIT() asm volatile("cp.async.commit_group;" ::: "memory")
#define CP_WAIT(n)  asm volatile("cp.async.wait_group %0;" :: "n"(n) : "memory")

__device__ __forceinline__ void ldm_x4(uint32_t* r, uint32_t addr) {
    asm volatile("ldmatrix.sync.aligned.m8n8.x4.shared.b16 {%0,%1,%2,%3}, [%4];"
                 : "=r"(r[0]), "=r"(r[1]), "=r"(r[2]), "=r"(r[3]) : "r"(addr));
}
__device__ __forceinline__ void mma_bf16(float* c, const uint32_t* a,
                                         const uint32_t* b) {
    asm volatile(
        "mma.sync.aligned.m16n8k16.row.col.f32.bf16.bf16.f32 "
        "{%0,%1,%2,%3},{%4,%5,%6,%7},{%8,%9},{%0,%1,%2,%3};"
        : "+f"(c[0]), "+f"(c[1]), "+f"(c[2]), "+f"(c[3])
        : "r"(a[0]), "r"(a[1]), "r"(a[2]), "r"(a[3]), "r"(b[0]), "r"(b[1]));
}

// ---------------------------------------------------------------------------
// Split kernels
// ---------------------------------------------------------------------------
__global__ void split_a_kernel(const float* __restrict__ A,
                               __nv_bfloat16* __restrict__ Ah,
                               __nv_bfloat16* __restrict__ Al, int n4)
{
    int i = blockIdx.x * blockDim.x + threadIdx.x;
    if (i >= n4) return;
    float4 v = ((const float4*)A)[i];
    __nv_bfloat16 h0 = __float2bfloat16_rn(v.x);
    __nv_bfloat16 h1 = __float2bfloat16_rn(v.y);
    __nv_bfloat16 h2 = __float2bfloat16_rn(v.z);
    __nv_bfloat16 h3 = __float2bfloat16_rn(v.w);
    __nv_bfloat162 hh0; hh0.x = h0; hh0.y = h1;
    __nv_bfloat162 hh1; hh1.x = h2; hh1.y = h3;
    ((__nv_bfloat162*)Ah)[2 * i]     = hh0;
    ((__nv_bfloat162*)Ah)[2 * i + 1] = hh1;
    __nv_bfloat162 ll0, ll1;
    ll0.x = __float2bfloat16_rn(v.x - __bfloat162float(h0));
    ll0.y = __float2bfloat16_rn(v.y - __bfloat162float(h1));
    ll1.x = __float2bfloat16_rn(v.z - __bfloat162float(h2));
    ll1.y = __float2bfloat16_rn(v.w - __bfloat162float(h3));
    ((__nv_bfloat162*)Al)[2 * i]     = ll0;
    ((__nv_bfloat162*)Al)[2 * i + 1] = ll1;
}

// W [K,N] fp32 -> Bh/Bl [N,K] bf16 (transpose + split)
__global__ void split_wT_kernel(const float* __restrict__ W,
                                __nv_bfloat16* __restrict__ Bh,
                                __nv_bfloat16* __restrict__ Bl, int K, int N)
{
    __shared__ float t[32][33];
    const int bx = blockIdx.x, by = blockIdx.y;
    const int tx = threadIdx.x, ty = threadIdx.y;
#pragma unroll
    for (int i = 0; i < 4; i++) {
        int k = by * 32 + ty + i * 8;
        t[ty + i * 8][tx] = W[(size_t)k * N + bx * 32 + tx];
    }
    __syncthreads();
#pragma unroll
    for (int i = 0; i < 4; i++) {
        int n = bx * 32 + ty + i * 8;
        int k = by * 32 + tx;
        float v = t[tx][ty + i * 8];
        __nv_bfloat16 h = __float2bfloat16_rn(v);
        Bh[(size_t)n * K + k] = h;
        Bl[(size_t)n * K + k] = __float2bfloat16_rn(v - __bfloat162float(h));
    }
}

// ---------------------------------------------------------------------------
// HMMA (mma.sync) split-bf16 GEMM:
//   C[M,N] = Ah@Bh^T + Ah@Bl^T + Al@Bh^T + bias
// A*: [M,K] bf16 row-major.  B*: [N,K] bf16 row-major.
// CTA 128x128, BK=32, 8 warps (2x4), warp tile 64x32, double-buffered cp.async.
// ---------------------------------------------------------------------------
constexpr int GP = 40;                     // smem pitch in bf16 (80B) — conflict-free
constexpr int GBUF = 128 * GP * 2;         // 10240 B per tile buffer
constexpr int GSTAGE = 4 * GBUF;           // Ah,Al,Bh,Bl per stage
constexpr size_t GM_SMEM = 2 * GSTAGE;     // 81920 B

__global__ void __launch_bounds__(256, 1) gemm_mma_kernel(
    const __nv_bfloat16* __restrict__ Ah, const __nv_bfloat16* __restrict__ Al,
    const __nv_bfloat16* __restrict__ Bh, const __nv_bfloat16* __restrict__ Bl,
    const float* __restrict__ bias, float* __restrict__ C, int N, int K)
{
    extern __shared__ char smem[];
    const uint32_t sb = smem_u32(smem);
    const int tid  = threadIdx.x;
    const int wid  = tid >> 5;
    const int lane = tid & 31;
    const int warp_m = wid >> 2;            // 0..1  (64 rows each)
    const int warp_n = wid & 3;             // 0..3  (32 cols each)
    const int row0 = blockIdx.y * 128;
    const int col0 = blockIdx.x * 128;

    float acc[4][4][4];
#pragma unroll
    for (int mt = 0; mt < 4; mt++)
#pragma unroll
        for (int nt = 0; nt < 4; nt++)
#pragma unroll
            for (int q = 0; q < 4; q++) acc[mt][nt][q] = 0.f;

    const int nChunks = K >> 5;             // BK=32

    // per-thread load mapping: 2 chunks of 16B per buffer
    const int lr0 = tid >> 2;               // rows tid/4 and +64
    const int lc  = (tid & 3) * 8;          // bf16 col offset (16B chunks)

    auto load_stage = [&](int s, int c) {
        const int k0 = c << 5;
        const uint32_t st = sb + s * GSTAGE;
#pragma unroll
        for (int i = 0; i < 2; i++) {
            const int r = lr0 + i * 64;
            const uint32_t so = r * (GP * 2) + lc * 2;
            const size_t ga = (size_t)(row0 + r) * K + k0 + lc;
            const size_t gb = (size_t)(col0 + r) * K + k0 + lc;
            cpasync16(st + 0 * GBUF + so, Ah + ga);
            cpasync16(st + 1 * GBUF + so, Al + ga);
            cpasync16(st + 2 * GBUF + so, Bh + gb);
            cpasync16(st + 3 * GBUF + so, Bl + gb);
        }
    };

    load_stage(0, 0);
    CP_COMMIT();

    // fragment smem addresses (byte offsets within a buffer)
    const int arow  = warp_m * 64 + (lane & 15);
    const int acolb = ((lane >> 4) & 1) * 16;
    const int bnrow = warp_n * 32 + (lane & 7) + ((lane >> 4) & 1) * 8;
    const int bcolb = ((lane >> 3) & 1) * 16;

    for (int c = 0; c < nChunks; c++) {
        const int cur = c & 1;
        if (c + 1 < nChunks) {
            load_stage(1 - cur, c + 1);
            CP_COMMIT();
            CP_WAIT(1);
        } else {
            CP_WAIT(0);
        }
        __syncthreads();

        const uint32_t st  = sb + cur * GSTAGE;
        const uint32_t sAh = st;
        const uint32_t sAl = st + GBUF;
        const uint32_t sBh = st + 2 * GBUF;
        const uint32_t sBl = st + 3 * GBUF;

#pragma unroll
        for (int ks = 0; ks < 2; ks++) {
            const int kb = ks * 32;   // byte offset of k16 step (16 bf16)
            uint32_t ah[4][4], al[4][4], bh[4][2], bl[4][2];
#pragma unroll
            for (int mt = 0; mt < 4; mt++) {
                const uint32_t ro = (uint32_t)(arow + mt * 16) * (GP * 2) + acolb + kb;
                ldm_x4(ah[mt], sAh + ro);
                ldm_x4(al[mt], sAl + ro);
            }
#pragma unroll
            for (int np = 0; np < 2; np++) {
                const uint32_t ro = (uint32_t)(bnrow + np * 16) * (GP * 2) + bcolb + kb;
                uint32_t t0[4], t1[4];
                ldm_x4(t0, sBh + ro);
                ldm_x4(t1, sBl + ro);
                bh[2 * np][0] = t0[0]; bh[2 * np][1] = t0[1];
                bh[2 * np + 1][0] = t0[2]; bh[2 * np + 1][1] = t0[3];
                bl[2 * np][0] = t1[0]; bl[2 * np][1] = t1[1];
                bl[2 * np + 1][0] = t1[2]; bl[2 * np + 1][1] = t1[3];
            }
#pragma unroll
            for (int mt = 0; mt < 4; mt++)
#pragma unroll
                for (int nt = 0; nt < 4; nt++) {
                    mma_bf16(acc[mt][nt], ah[mt], bh[nt]);
                    mma_bf16(acc[mt][nt], ah[mt], bl[nt]);
                    mma_bf16(acc[mt][nt], al[mt], bh[nt]);
                }
        }
        __syncthreads();
    }

    // epilogue: fused bias, float2 stores
    const int g  = lane >> 2;
    const int tc = (lane & 3) * 2;
#pragma unroll
    for (int nt = 0; nt < 4; nt++) {
        const int cg = col0 + warp_n * 32 + nt * 8 + tc;
        const float bx = bias[cg];
        const float by = bias[cg + 1];
#pragma unroll
        for (int mt = 0; mt < 4; mt++) {
            const int rg = row0 + warp_m * 64 + mt * 16 + g;
            float2 v0, v1;
            v0.x = acc[mt][nt][0] + bx;  v0.y = acc[mt][nt][1] + by;
            v1.x = acc[mt][nt][2] + bx;  v1.y = acc[mt][nt][3] + by;
            *(float2*)(C + (size_t)rg * N + cg)       = v0;
            *(float2*)(C + (size_t)(rg + 8) * N + cg) = v1;
        }
    }
}

// ----------------------------------------------------------------------------
// Flash attention (fp32, causal) — unchanged (proven correct)
// ----------------------------------------------------------------------------
constexpr int LDQ  = 68;
constexpr int LDS_ = 65;
constexpr int RED_P = 17;

constexpr int ATTN_SMEM_FLOATS =
    64 * LDQ + 64 * LDQ + 64 * LDS_ + 64 * RED_P + 64 + 64 + 64;
constexpr size_t ATTN_SMEM_BYTES = (size_t)ATTN_SMEM_FLOATS * sizeof(float);

__global__ void __launch_bounds__(256) attn_kernel(
    const float* __restrict__ qkv, float* __restrict__ out)
{
    extern __shared__ float smemf[];
    float* Qt   = smemf;
    float* KV   = Qt + 64 * LDQ;
    float* St   = KV + 64 * LDQ;
    float* red  = St + 64 * LDS_;
    float* mrow = red + 64 * RED_P;
    float* lrow = mrow + 64;
    float* arow = lrow + 64;

    const int qt = blockIdx.x;
    const int h  = blockIdx.y;
    const int b  = blockIdx.z;
    const int tid = threadIdx.x;
    const int tx = tid & 15;
    const int ty = tid >> 4;
    const int lane_r = ty * 4;
    const int lane_c = tx * 4;
    const size_t rowstride = (size_t)QKV_N;

    const float* qbase = qkv + (size_t)(b * L_ + qt * 64) * rowstride + h * HD_;
#pragma unroll
    for (int u = 0; u < 4; u++) {
        const int i = u * 16 + ty;
        const int d = tx * 4;
        float4 v = *(const float4*)(qbase + (size_t)i * rowstride + d);
        Qt[(d + 0) * LDQ + i] = v.x;
        Qt[(d + 1) * LDQ + i] = v.y;
        Qt[(d + 2) * LDQ + i] = v.z;
        Qt[(d + 3) * LDQ + i] = v.w;
    }
    if (tid < 64) { mrow[tid] = -CUDART_INF_F; lrow[tid] = 0.f; }

    float o[4][4];
#pragma unroll
    for (int r = 0; r < 4; r++)
#pragma unroll
        for (int c = 0; c < 4; c++) o[r][c] = 0.f;

    const float scale = 0.125f;
    __syncthreads();

    for (int kt = 0; kt <= qt; kt++) {
        const float* kbase =
            qkv + (size_t)(b * L_ + kt * 64) * rowstride + D_ + h * HD_;
#pragma unroll
        for (int u = 0; u < 4; u++) {
            const int j = u * 16 + ty;
            const int d = tx * 4;
            float4 v = *(const float4*)(kbase + (size_t)j * rowstride + d);
            KV[(d + 0) * LDQ + j] = v.x;
            KV[(d + 1) * LDQ + j] = v.y;
            KV[(d + 2) * LDQ + j] = v.z;
            KV[(d + 3) * LDQ + j] = v.w;
        }
        __syncthreads();

        float s[4][4];
#pragma unroll
        for (int r = 0; r < 4; r++)
#pragma unroll
            for (int c = 0; c < 4; c++) s[r][c] = 0.f;

#pragma unroll 8
        for (int d = 0; d < 64; d++) {
            float qv[4], kv[4];
            *(float4*)qv = *(const float4*)&Qt[d * LDQ + lane_r];
            *(float4*)kv = *(const float4*)&KV[d * LDQ + lane_c];
#pragma unroll
            for (int r = 0; r < 4; r++)
#pragma unroll
                for (int c = 0; c < 4; c++)
                    s[r][c] += qv[r] * kv[c];
        }

        const bool diag = (kt == qt);
#pragma unroll
        for (int r = 0; r < 4; r++)
#pragma unroll
            for (int c = 0; c < 4; c++) {
                float v = s[r][c] * scale;
                if (diag && (lane_c + c > lane_r + r)) v = -CUDART_INF_F;
                s[r][c] = v;
            }

#pragma unroll
        for (int r = 0; r < 4; r++) {
            float m = fmaxf(fmaxf(s[r][0], s[r][1]), fmaxf(s[r][2], s[r][3]));
            red[(lane_r + r) * RED_P + tx] = m;
        }
        __syncthreads();

        const float* vbase =
            qkv + (size_t)(b * L_ + kt * 64) * rowstride + 2 * D_ + h * HD_;
#pragma unroll
        for (int u = 0; u < 4; u++) {
            const int k = u * 16 + ty;
            const int c = tx * 4;
            *(float4*)&KV[k * LDQ + c] =
                *(const float4*)(vbase + (size_t)k * rowstride + c);
        }
        if (tid < 64) {
            float m = red[tid * RED_P + 0];
#pragma unroll
            for (int t = 1; t < 16; t++) m = fmaxf(m, red[tid * RED_P + t]);
            const float mo = mrow[tid];
            const float mn = fmaxf(mo, m);
            mrow[tid] = mn;
            arow[tid] = __expf(mo - mn);
        }
        __syncthreads();

#pragma unroll
        for (int r = 0; r < 4; r++) {
            const float mn = mrow[lane_r + r];
            float rs = 0.f;
#pragma unroll
            for (int c = 0; c < 4; c++) {
                const float p = __expf(s[r][c] - mn);
                St[(lane_c + c) * LDS_ + lane_r + r] = p;
                rs += p;
            }
            red[(lane_r + r) * RED_P + tx] = rs;
        }
        __syncthreads();

        if (tid < 64) {
            float sum = 0.f;
#pragma unroll
            for (int t = 0; t < 16; t++) sum += red[tid * RED_P + t];
            lrow[tid] = arow[tid] * lrow[tid] + sum;
        }

#pragma unroll
        for (int r = 0; r < 4; r++) {
            const float a = arow[lane_r + r];
#pragma unroll
            for (int c = 0; c < 4; c++) o[r][c] *= a;
        }

#pragma unroll 4
        for (int k = 0; k < 64; k++) {
            float pv[4], vv[4];
#pragma unroll
            for (int r = 0; r < 4; r++) pv[r] = St[k * LDS_ + lane_r + r];
            *(float4*)vv = *(const float4*)&KV[k * LDQ + lane_c];
#pragma unroll
            for (int r = 0; r < 4; r++)
#pragma unroll
                for (int c = 0; c < 4; c++)
                    o[r][c] += pv[r] * vv[c];
        }
        __syncthreads();
    }

#pragma unroll
    for (int r = 0; r < 4; r++) {
        const float inv = 1.0f / lrow[lane_r + r];
        float4 v;
        v.x = o[r][0] * inv;
        v.y = o[r][1] * inv;
        v.z = o[r][2] * inv;
        v.w = o[r][3] * inv;
        *(float4*)(out + (size_t)(b * L_ + qt * 64 + lane_r + r) * D_ +
                   h * HD_ + lane_c) = v;
    }
}

// ----------------------------------------------------------------------------
// Launch
// ----------------------------------------------------------------------------
extern "C" void kernel_launch(void* const* d_in, const int* in_sizes, int n_in,
                              void* d_out, int out_size)
{
    const float* x     = (const float*)d_in[0];
    const float* Wqkv  = (const float*)d_in[1];
    const float* bqkv  = (const float*)d_in[2];
    const float* Wproj = (const float*)d_in[3];
    const float* bproj = (const float*)d_in[4];
    float* out = (float*)d_out;

    float *qkv, *att;
    __nv_bfloat16 *xhi, *xlo, *ahi, *alo, *wqh, *wql, *wph, *wpl;
    cudaGetSymbolAddress((void**)&qkv, g_qkv);
    cudaGetSymbolAddress((void**)&att, g_att);
    cudaGetSymbolAddress((void**)&xhi, g_xhi);
    cudaGetSymbolAddress((void**)&xlo, g_xlo);
    cudaGetSymbolAddress((void**)&ahi, g_ahi);
    cudaGetSymbolAddress((void**)&alo, g_alo);
    cudaGetSymbolAddress((void**)&wqh, g_wqh);
    cudaGetSymbolAddress((void**)&wql, g_wql);
    cudaGetSymbolAddress((void**)&wph, g_wph);
    cudaGetSymbolAddress((void**)&wpl, g_wpl);

    static bool attr_set = false;
    if (!attr_set) {
        cudaFuncSetAttribute(attn_kernel,
                             cudaFuncAttributeMaxDynamicSharedMemorySize,
                             (int)ATTN_SMEM_BYTES);
        cudaFuncSetAttribute(gemm_mma_kernel,
                             cudaFuncAttributeMaxDynamicSharedMemorySize,
                             (int)GM_SMEM);
        attr_set = true;
    }

    const int n4x = M_ * D_ / 4;

    // split inputs
    split_a_kernel<<<(n4x + 255) / 256, 256>>>(x, xhi, xlo, n4x);
    split_wT_kernel<<<dim3(QKV_N / 32, D_ / 32), dim3(32, 8)>>>(Wqkv, wqh, wql, D_, QKV_N);
    split_wT_kernel<<<dim3(D_ / 32, D_ / 32), dim3(32, 8)>>>(Wproj, wph, wpl, D_, D_);

    // 1) QKV projection (HMMA)
    gemm_mma_kernel<<<dim3(QKV_N / 128, M_ / 128), 256, GM_SMEM>>>(
        xhi, xlo, wqh, wql, bqkv, qkv, QKV_N, D_);

    // 2) causal flash attention (fp32 SIMT)
    attn_kernel<<<dim3(L_ / 64, H_, B_), 256, ATTN_SMEM_BYTES>>>(qkv, att);

    // 3) output projection (HMMA)
    split_a_kernel<<<(n4x + 255) / 256, 256>>>(att, ahi, alo, n4x);
    gemm_mma_kernel<<<dim3(D_ / 128, M_ / 128), 256, GM_SMEM>>>(
        ahi, alo, wph, wpl, bproj, out, D_, D_);
}

// round 6
// speedup vs baseline: 2.5697x; 1.7822x over previous
#include <cuda_runtime.h>
#include <cuda_bf16.h>
#include <math_constants.h>
#include <cstdint>

// Problem constants
constexpr int B_  = 4;
constexpr int L_  = 2048;
constexpr int D_  = 1024;
constexpr int H_  = 16;
constexpr int HD_ = 64;
constexpr int M_  = B_ * L_;       // 8192
constexpr int QKV_N = 3 * D_;      // 3072

// ---------------------------------------------------------------------------
// Scratch (allocation-free -> __device__ globals)
// ---------------------------------------------------------------------------
__device__ __nv_bfloat16 g_xhi[(size_t)M_ * D_];
__device__ __nv_bfloat16 g_xlo[(size_t)M_ * D_];
__device__ __nv_bfloat16 g_qkvh[(size_t)M_ * QKV_N];   // qkv hi (bf16)
__device__ __nv_bfloat16 g_qkvl[(size_t)M_ * QKV_N];   // qkv lo
__device__ __nv_bfloat16 g_ahi[(size_t)M_ * D_];       // attn out hi
__device__ __nv_bfloat16 g_alo[(size_t)M_ * D_];       // attn out lo
__device__ __nv_bfloat16 g_wqh[(size_t)QKV_N * D_];    // Wqkv^T [N,K]
__device__ __nv_bfloat16 g_wql[(size_t)QKV_N * D_];
__device__ __nv_bfloat16 g_wph[(size_t)D_ * D_];       // Wproj^T [N,K]
__device__ __nv_bfloat16 g_wpl[(size_t)D_ * D_];

// ---------------------------------------------------------------------------
// PTX helpers
// ---------------------------------------------------------------------------
__device__ __forceinline__ uint32_t smem_u32(const void* p) {
    uint32_t a;
    asm("{ .reg .u64 t; cvta.to.shared.u64 t, %1; cvt.u32.u64 %0, t; }"
        : "=r"(a) : "l"(p));
    return a;
}
__device__ __forceinline__ void cpasync16(uint32_t saddr, const void* g) {
    asm volatile("cp.async.cg.shared.global [%0], [%1], 16;" :: "r"(saddr), "l"(g));
}
#define CP_COMMIT() asm volatile("cp.async.commit_group;" ::: "memory")
#define CP_WAIT(n)  asm volatile("cp.async.wait_group %0;" :: "n"(n) : "memory")

__device__ __forceinline__ void ldm_x4(uint32_t* r, uint32_t addr) {
    asm volatile("ldmatrix.sync.aligned.m8n8.x4.shared.b16 {%0,%1,%2,%3}, [%4];"
                 : "=r"(r[0]), "=r"(r[1]), "=r"(r[2]), "=r"(r[3]) : "r"(addr));
}
__device__ __forceinline__ void ldm_x4_t(uint32_t* r, uint32_t addr) {
    asm volatile("ldmatrix.sync.aligned.m8n8.x4.trans.shared.b16 {%0,%1,%2,%3}, [%4];"
                 : "=r"(r[0]), "=r"(r[1]), "=r"(r[2]), "=r"(r[3]) : "r"(addr));
}
__device__ __forceinline__ void mma_bf16(float* c, const uint32_t* a,
                                         const uint32_t* b) {
    asm volatile(
        "mma.sync.aligned.m16n8k16.row.col.f32.bf16.bf16.f32 "
        "{%0,%1,%2,%3},{%4,%5,%6,%7},{%8,%9},{%0,%1,%2,%3};"
        : "+f"(c[0]), "+f"(c[1]), "+f"(c[2]), "+f"(c[3])
        : "r"(a[0]), "r"(a[1]), "r"(a[2]), "r"(a[3]), "r"(b[0]), "r"(b[1]));
}
// pack two fp32 into bf16x2 hi + residual lo
__device__ __forceinline__ void pack_hilo(float x, float y,
                                          uint32_t& hi, uint32_t& lo) {
    __nv_bfloat162 h2 = __floats2bfloat162_rn(x, y);
    float2 f2 = __bfloat1622float2(h2);
    __nv_bfloat162 l2 = __floats2bfloat162_rn(x - f2.x, y - f2.y);
    hi = *(uint32_t*)&h2;
    lo = *(uint32_t*)&l2;
}

// ---------------------------------------------------------------------------
// Split kernels
// ---------------------------------------------------------------------------
__global__ void split_a_kernel(const float* __restrict__ A,
                               __nv_bfloat16* __restrict__ Ah,
                               __nv_bfloat16* __restrict__ Al, int n4)
{
    int i = blockIdx.x * blockDim.x + threadIdx.x;
    if (i >= n4) return;
    float4 v = ((const float4*)A)[i];
    uint32_t h0, l0, h1, l1;
    pack_hilo(v.x, v.y, h0, l0);
    pack_hilo(v.z, v.w, h1, l1);
    ((uint32_t*)Ah)[2 * i]     = h0;
    ((uint32_t*)Ah)[2 * i + 1] = h1;
    ((uint32_t*)Al)[2 * i]     = l0;
    ((uint32_t*)Al)[2 * i + 1] = l1;
}

// W [K,N] fp32 -> Bh/Bl [N,K] bf16 (transpose + split)
__global__ void split_wT_kernel(const float* __restrict__ W,
                                __nv_bfloat16* __restrict__ Bh,
                                __nv_bfloat16* __restrict__ Bl, int K, int N)
{
    __shared__ float t[32][33];
    const int bx = blockIdx.x, by = blockIdx.y;
    const int tx = threadIdx.x, ty = threadIdx.y;
#pragma unroll
    for (int i = 0; i < 4; i++) {
        int k = by * 32 + ty + i * 8;
        t[ty + i * 8][tx] = W[(size_t)k * N + bx * 32 + tx];
    }
    __syncthreads();
#pragma unroll
    for (int i = 0; i < 4; i++) {
        int n = bx * 32 + ty + i * 8;
        int k = by * 32 + tx;
        float v = t[tx][ty + i * 8];
        __nv_bfloat16 h = __float2bfloat16_rn(v);
        Bh[(size_t)n * K + k] = h;
        Bl[(size_t)n * K + k] = __float2bfloat16_rn(v - __bfloat162float(h));
    }
}

// ---------------------------------------------------------------------------
// HMMA split-bf16 GEMM. SPLIT_OUT: write bf16 hi/lo instead of fp32.
// ---------------------------------------------------------------------------
constexpr int GP = 40;
constexpr int GBUF = 128 * GP * 2;
constexpr int GSTAGE = 4 * GBUF;
constexpr size_t GM_SMEM = 2 * GSTAGE;     // 81920 B

template <bool SPLIT_OUT>
__global__ void __launch_bounds__(256, 1) gemm_mma_kernel(
    const __nv_bfloat16* __restrict__ Ah, const __nv_bfloat16* __restrict__ Al,
    const __nv_bfloat16* __restrict__ Bh, const __nv_bfloat16* __restrict__ Bl,
    const float* __restrict__ bias, float* __restrict__ C,
    __nv_bfloat16* __restrict__ Ch, __nv_bfloat16* __restrict__ Cl,
    int N, int K)
{
    extern __shared__ char smem[];
    const uint32_t sb = smem_u32(smem);
    const int tid  = threadIdx.x;
    const int wid  = tid >> 5;
    const int lane = tid & 31;
    const int warp_m = wid >> 2;
    const int warp_n = wid & 3;
    const int row0 = blockIdx.y * 128;
    const int col0 = blockIdx.x * 128;

    float acc[4][4][4];
#pragma unroll
    for (int mt = 0; mt < 4; mt++)
#pragma unroll
        for (int nt = 0; nt < 4; nt++)
#pragma unroll
            for (int q = 0; q < 4; q++) acc[mt][nt][q] = 0.f;

    const int nChunks = K >> 5;
    const int lr0 = tid >> 2;
    const int lc  = (tid & 3) * 8;

    auto load_stage = [&](int s, int c) {
        const int k0 = c << 5;
        const uint32_t st = sb + s * GSTAGE;
#pragma unroll
        for (int i = 0; i < 2; i++) {
            const int r = lr0 + i * 64;
            const uint32_t so = r * (GP * 2) + lc * 2;
            const size_t ga = (size_t)(row0 + r) * K + k0 + lc;
            const size_t gb = (size_t)(col0 + r) * K + k0 + lc;
            cpasync16(st + 0 * GBUF + so, Ah + ga);
            cpasync16(st + 1 * GBUF + so, Al + ga);
            cpasync16(st + 2 * GBUF + so, Bh + gb);
            cpasync16(st + 3 * GBUF + so, Bl + gb);
        }
    };

    load_stage(0, 0);
    CP_COMMIT();

    const int arow  = warp_m * 64 + (lane & 15);
    const int acolb = ((lane >> 4) & 1) * 16;
    const int bnrow = warp_n * 32 + (lane & 7) + ((lane >> 4) & 1) * 8;
    const int bcolb = ((lane >> 3) & 1) * 16;

    for (int c = 0; c < nChunks; c++) {
        const int cur = c & 1;
        if (c + 1 < nChunks) {
            load_stage(1 - cur, c + 1);
            CP_COMMIT();
            CP_WAIT(1);
        } else {
            CP_WAIT(0);
        }
        __syncthreads();

        const uint32_t st  = sb + cur * GSTAGE;
        const uint32_t sAh = st;
        const uint32_t sAl = st + GBUF;
        const uint32_t sBh = st + 2 * GBUF;
        const uint32_t sBl = st + 3 * GBUF;

#pragma unroll
        for (int ks = 0; ks < 2; ks++) {
            const int kb = ks * 32;
            uint32_t ah[4][4], al[4][4], bh[4][2], bl[4][2];
#pragma unroll
            for (int mt = 0; mt < 4; mt++) {
                const uint32_t ro = (uint32_t)(arow + mt * 16) * (GP * 2) + acolb + kb;
                ldm_x4(ah[mt], sAh + ro);
                ldm_x4(al[mt], sAl + ro);
            }
#pragma unroll
            for (int np = 0; np < 2; np++) {
                const uint32_t ro = (uint32_t)(bnrow + np * 16) * (GP * 2) + bcolb + kb;
                uint32_t t0[4], t1[4];
                ldm_x4(t0, sBh + ro);
                ldm_x4(t1, sBl + ro);
                bh[2 * np][0] = t0[0]; bh[2 * np][1] = t0[1];
                bh[2 * np + 1][0] = t0[2]; bh[2 * np + 1][1] = t0[3];
                bl[2 * np][0] = t1[0]; bl[2 * np][1] = t1[1];
                bl[2 * np + 1][0] = t1[2]; bl[2 * np + 1][1] = t1[3];
            }
#pragma unroll
            for (int mt = 0; mt < 4; mt++)
#pragma unroll
                for (int nt = 0; nt < 4; nt++) {
                    mma_bf16(acc[mt][nt], ah[mt], bh[nt]);
                    mma_bf16(acc[mt][nt], ah[mt], bl[nt]);
                    mma_bf16(acc[mt][nt], al[mt], bh[nt]);
                }
        }
        __syncthreads();
    }

    const int g  = lane >> 2;
    const int tc = (lane & 3) * 2;
#pragma unroll
    for (int nt = 0; nt < 4; nt++) {
        const int cg = col0 + warp_n * 32 + nt * 8 + tc;
        const float bx = bias[cg];
        const float by = bias[cg + 1];
#pragma unroll
        for (int mt = 0; mt < 4; mt++) {
            const int rg = row0 + warp_m * 64 + mt * 16 + g;
            float v00 = acc[mt][nt][0] + bx, v01 = acc[mt][nt][1] + by;
            float v10 = acc[mt][nt][2] + bx, v11 = acc[mt][nt][3] + by;
            if (SPLIT_OUT) {
                uint32_t h0, l0, h1, l1;
                pack_hilo(v00, v01, h0, l0);
                pack_hilo(v10, v11, h1, l1);
                *(uint32_t*)(Ch + (size_t)rg * N + cg)       = h0;
                *(uint32_t*)(Cl + (size_t)rg * N + cg)       = l0;
                *(uint32_t*)(Ch + (size_t)(rg + 8) * N + cg) = h1;
                *(uint32_t*)(Cl + (size_t)(rg + 8) * N + cg) = l1;
            } else {
                float2 a0; a0.x = v00; a0.y = v01;
                float2 a1; a1.x = v10; a1.y = v11;
                *(float2*)(C + (size_t)rg * N + cg)       = a0;
                *(float2*)(C + (size_t)(rg + 8) * N + cg) = a1;
            }
        }
    }
}

// ---------------------------------------------------------------------------
// Tensor-core flash attention (causal). CTA = 128 q-rows x (b,h). 8 warps.
// K/V tiles of 64 keys, double-buffered cp.async.
// S = QhKh+QhKl+QlKh ; PV = PhVh+PhVl+PlVh ; fp32 accum throughout.
// ---------------------------------------------------------------------------
constexpr int APB      = 144;               // smem pitch bytes (72 bf16)
constexpr int AT_QB    = 128 * APB;         // 18432 per Q tensor
constexpr int AT_KVT   = 64 * APB;          // 9216 per K/V tensor tile
constexpr int AT_STAGE = 4 * AT_KVT;        // 36864
constexpr size_t AT_SMEM = 2 * (size_t)AT_QB + 2 * (size_t)AT_STAGE;  // 110592

__global__ void __launch_bounds__(256, 1) attn_mma_kernel(
    const __nv_bfloat16* __restrict__ qkvh,
    const __nv_bfloat16* __restrict__ qkvl,
    __nv_bfloat16* __restrict__ outh,
    __nv_bfloat16* __restrict__ outl)
{
    extern __shared__ char smem[];
    const uint32_t sb = smem_u32(smem);
    const uint32_t sQh = sb;
    const uint32_t sQl = sb + AT_QB;
    const uint32_t sS0 = sb + 2 * AT_QB;

    const int qb = blockIdx.x;              // q-tile (128 rows)
    const int h  = blockIdx.y;
    const int b  = blockIdx.z;
    const int tid  = threadIdx.x;
    const int wid  = tid >> 5;
    const int lane = tid & 31;

    const size_t qrow0 = (size_t)(b * L_ + qb * 128);

    // ---- Q hi/lo -> smem ----
#pragma unroll
    for (int i = 0; i < 4; i++) {
        const int id = i * 256 + tid;
        const int r = id >> 3, s = id & 7;
        const size_t g = (qrow0 + r) * QKV_N + h * HD_ + s * 8;
        const uint32_t so = r * APB + s * 16;
        cpasync16(sQh + so, qkvh + g);
        cpasync16(sQl + so, qkvl + g);
    }
    CP_COMMIT();

    const int nkt = 2 * qb + 2;

    auto load_kv = [&](int buf, int kt) {
        const uint32_t st = sS0 + buf * AT_STAGE;
        const size_t krow0 = (size_t)(b * L_ + kt * 64);
#pragma unroll
        for (int i = 0; i < 2; i++) {
            const int id = i * 256 + tid;
            const int r = id >> 3, s = id & 7;
            const size_t gk = (krow0 + r) * QKV_N + D_ + h * HD_ + s * 8;
            const size_t gv = gk + D_;
            const uint32_t so = r * APB + s * 16;
            cpasync16(st + 0 * AT_KVT + so, qkvh + gk);
            cpasync16(st + 1 * AT_KVT + so, qkvl + gk);
            cpasync16(st + 2 * AT_KVT + so, qkvh + gv);
            cpasync16(st + 3 * AT_KVT + so, qkvl + gv);
        }
    };

    load_kv(0, 0);
    CP_COMMIT();

    // ---- Q fragments (after Q group done) ----
    CP_WAIT(1);
    __syncthreads();
    uint32_t qh[4][4], ql[4][4];
    {
        const uint32_t base = (uint32_t)(wid * 16 + (lane & 15)) * APB +
                              ((lane >> 4) & 1) * 16;
#pragma unroll
        for (int j = 0; j < 4; j++) {
            ldm_x4(qh[j], sQh + base + j * 32);
            ldm_x4(ql[j], sQl + base + j * 32);
        }
    }

    float o[8][4];
#pragma unroll
    for (int nt = 0; nt < 8; nt++)
#pragma unroll
        for (int q = 0; q < 4; q++) o[nt][q] = 0.f;
    float m0 = -CUDART_INF_F, m1 = -CUDART_INF_F;
    float l0 = 0.f, l1 = 0.f;

    const int row_r0 = qb * 128 + wid * 16 + (lane >> 2);  // global q row (and +8)
    const int ccol   = 2 * (lane & 3);
    constexpr float SCALE = 0.125f;
    constexpr float LOG2E = 1.44269504f;

    for (int kt = 0; kt < nkt; kt++) {
        const int buf = kt & 1;
        if (kt + 1 < nkt) {
            load_kv(1 - buf, kt + 1);
            CP_COMMIT();
            CP_WAIT(1);
        } else {
            CP_WAIT(0);
        }
        __syncthreads();

        const uint32_t st  = sS0 + buf * AT_STAGE;
        const uint32_t sKh = st;
        const uint32_t sKl = st + AT_KVT;
        const uint32_t sVh = st + 2 * AT_KVT;
        const uint32_t sVl = st + 3 * AT_KVT;

        // ---- S = Q K^T (3 split passes) ----
        float s[8][4];
#pragma unroll
        for (int nt = 0; nt < 8; nt++)
#pragma unroll
            for (int q = 0; q < 4; q++) s[nt][q] = 0.f;

        const uint32_t kbase = (uint32_t)((lane & 7) + ((lane >> 4) & 1) * 8) * APB +
                               ((lane >> 3) & 1) * 16;
#pragma unroll
        for (int j = 0; j < 4; j++) {
            uint32_t kh[8][2], kl[8][2];
#pragma unroll
            for (int np = 0; np < 4; np++) {
                const uint32_t ro = kbase + (uint32_t)(np * 16) * APB + j * 32;
                uint32_t t0[4], t1[4];
                ldm_x4(t0, sKh + ro);
                ldm_x4(t1, sKl + ro);
                kh[2 * np][0] = t0[0]; kh[2 * np][1] = t0[1];
                kh[2 * np + 1][0] = t0[2]; kh[2 * np + 1][1] = t0[3];
                kl[2 * np][0] = t1[0]; kl[2 * np][1] = t1[1];
                kl[2 * np + 1][0] = t1[2]; kl[2 * np + 1][1] = t1[3];
            }
#pragma unroll
            for (int nt = 0; nt < 8; nt++) {
                mma_bf16(s[nt], qh[j], kh[nt]);
                mma_bf16(s[nt], qh[j], kl[nt]);
                mma_bf16(s[nt], ql[j], kh[nt]);
            }
        }

        // ---- scale + causal mask ----
#pragma unroll
        for (int nt = 0; nt < 8; nt++)
#pragma unroll
            for (int q = 0; q < 4; q++) s[nt][q] *= SCALE;

        if (kt >= 2 * qb) {
#pragma unroll
            for (int nt = 0; nt < 8; nt++) {
                const int col = kt * 64 + nt * 8 + ccol;
                if (col > row_r0)         s[nt][0] = -CUDART_INF_F;
                if (col + 1 > row_r0)     s[nt][1] = -CUDART_INF_F;
                if (col > row_r0 + 8)     s[nt][2] = -CUDART_INF_F;
                if (col + 1 > row_r0 + 8) s[nt][3] = -CUDART_INF_F;
            }
        }

        // ---- online softmax ----
        float tm0 = -CUDART_INF_F, tm1 = -CUDART_INF_F;
#pragma unroll
        for (int nt = 0; nt < 8; nt++) {
            tm0 = fmaxf(tm0, fmaxf(s[nt][0], s[nt][1]));
            tm1 = fmaxf(tm1, fmaxf(s[nt][2], s[nt][3]));
        }
        tm0 = fmaxf(tm0, __shfl_xor_sync(0xffffffffu, tm0, 1));
        tm0 = fmaxf(tm0, __shfl_xor_sync(0xffffffffu, tm0, 2));
        tm1 = fmaxf(tm1, __shfl_xor_sync(0xffffffffu, tm1, 1));
        tm1 = fmaxf(tm1, __shfl_xor_sync(0xffffffffu, tm1, 2));

        const float mn0 = fmaxf(m0, tm0);
        const float mn1 = fmaxf(m1, tm1);
        const float a0 = exp2f((m0 - mn0) * LOG2E);
        const float a1 = exp2f((m1 - mn1) * LOG2E);
        m0 = mn0; m1 = mn1;

        float rs0 = 0.f, rs1 = 0.f;
#pragma unroll
        for (int nt = 0; nt < 8; nt++) {
            float p0 = exp2f((s[nt][0] - mn0) * LOG2E);
            float p1 = exp2f((s[nt][1] - mn0) * LOG2E);
            float p2 = exp2f((s[nt][2] - mn1) * LOG2E);
            float p3 = exp2f((s[nt][3] - mn1) * LOG2E);
            s[nt][0] = p0; s[nt][1] = p1; s[nt][2] = p2; s[nt][3] = p3;
            rs0 += p0 + p1;
            rs1 += p2 + p3;
        }
        rs0 += __shfl_xor_sync(0xffffffffu, rs0, 1);
        rs0 += __shfl_xor_sync(0xffffffffu, rs0, 2);
        rs1 += __shfl_xor_sync(0xffffffffu, rs1, 1);
        rs1 += __shfl_xor_sync(0xffffffffu, rs1, 2);
        l0 = a0 * l0 + rs0;
        l1 = a1 * l1 + rs1;

#pragma unroll
        for (int nt = 0; nt < 8; nt++) {
            o[nt][0] *= a0; o[nt][1] *= a0;
            o[nt][2] *= a1; o[nt][3] *= a1;
        }

        // ---- pack P (C-frag -> A-frag identity) ----
        uint32_t ph[4][4], pl[4][4];
#pragma unroll
        for (int j = 0; j < 4; j++) {
            pack_hilo(s[2 * j][0],     s[2 * j][1],     ph[j][0], pl[j][0]);
            pack_hilo(s[2 * j][2],     s[2 * j][3],     ph[j][1], pl[j][1]);
            pack_hilo(s[2 * j + 1][0], s[2 * j + 1][1], ph[j][2], pl[j][2]);
            pack_hilo(s[2 * j + 1][2], s[2 * j + 1][3], ph[j][3], pl[j][3]);
        }

        // ---- O += P V (3 split passes); V via ldmatrix.trans ----
        const int vmat = lane >> 3;
        const uint32_t vrowb = (uint32_t)((vmat & 1) * 8 + (lane & 7)) * APB +
                               (vmat >> 1) * 16;
#pragma unroll
        for (int j = 0; j < 4; j++) {
            uint32_t vh[8][2], vl[8][2];
#pragma unroll
            for (int pp = 0; pp < 4; pp++) {
                const uint32_t ro = vrowb + (uint32_t)(j * 16) * APB + pp * 32;
                uint32_t t0[4], t1[4];
                ldm_x4_t(t0, sVh + ro);
                ldm_x4_t(t1, sVl + ro);
                vh[2 * pp][0] = t0[0]; vh[2 * pp][1] = t0[1];
                vh[2 * pp + 1][0] = t0[2]; vh[2 * pp + 1][1] = t0[3];
                vl[2 * pp][0] = t1[0]; vl[2 * pp][1] = t1[1];
                vl[2 * pp + 1][0] = t1[2]; vl[2 * pp + 1][1] = t1[3];
            }
#pragma unroll
            for (int nt = 0; nt < 8; nt++) {
                mma_bf16(o[nt], ph[j], vh[nt]);
                mma_bf16(o[nt], ph[j], vl[nt]);
                mma_bf16(o[nt], pl[j], vh[nt]);
            }
        }
        __syncthreads();
    }

    // ---- finalize: /l, split hi/lo, store ----
    const float inv0 = 1.0f / l0;
    const float inv1 = 1.0f / l1;
    const size_t grow0 = qrow0 + wid * 16 + (lane >> 2);
#pragma unroll
    for (int nt = 0; nt < 8; nt++) {
        const int col = h * HD_ + nt * 8 + ccol;
        uint32_t h0, lo0, h1, lo1;
        pack_hilo(o[nt][0] * inv0, o[nt][1] * inv0, h0, lo0);
        pack_hilo(o[nt][2] * inv1, o[nt][3] * inv1, h1, lo1);
        *(uint32_t*)(outh + grow0 * D_ + col)       = h0;
        *(uint32_t*)(outl + grow0 * D_ + col)       = lo0;
        *(uint32_t*)(outh + (grow0 + 8) * D_ + col) = h1;
        *(uint32_t*)(outl + (grow0 + 8) * D_ + col) = lo1;
    }
}

// ----------------------------------------------------------------------------
// Launch
// ----------------------------------------------------------------------------
extern "C" void kernel_launch(void* const* d_in, const int* in_sizes, int n_in,
                              void* d_out, int out_size)
{
    const float* x     = (const float*)d_in[0];
    const float* Wqkv  = (const float*)d_in[1];
    const float* bqkv  = (const float*)d_in[2];
    const float* Wproj = (const float*)d_in[3];
    const float* bproj = (const float*)d_in[4];
    float* out = (float*)d_out;

    __nv_bfloat16 *xhi, *xlo, *qkvh, *qkvl, *ahi, *alo, *wqh, *wql, *wph, *wpl;
    cudaGetSymbolAddress((void**)&xhi, g_xhi);
    cudaGetSymbolAddress((void**)&xlo, g_xlo);
    cudaGetSymbolAddress((void**)&qkvh, g_qkvh);
    cudaGetSymbolAddress((void**)&qkvl, g_qkvl);
    cudaGetSymbolAddress((void**)&ahi, g_ahi);
    cudaGetSymbolAddress((void**)&alo, g_alo);
    cudaGetSymbolAddress((void**)&wqh, g_wqh);
    cudaGetSymbolAddress((void**)&wql, g_wql);
    cudaGetSymbolAddress((void**)&wph, g_wph);
    cudaGetSymbolAddress((void**)&wpl, g_wpl);

    static bool attr_set = false;
    if (!attr_set) {
        cudaFuncSetAttribute(gemm_mma_kernel<true>,
                             cudaFuncAttributeMaxDynamicSharedMemorySize,
                             (int)GM_SMEM);
        cudaFuncSetAttribute(gemm_mma_kernel<false>,
                             cudaFuncAttributeMaxDynamicSharedMemorySize,
                             (int)GM_SMEM);
        cudaFuncSetAttribute(attn_mma_kernel,
                             cudaFuncAttributeMaxDynamicSharedMemorySize,
                             (int)AT_SMEM);
        attr_set = true;
    }

    const int n4x = M_ * D_ / 4;

    // prep: splits
    split_a_kernel<<<(n4x + 255) / 256, 256>>>(x, xhi, xlo, n4x);
    split_wT_kernel<<<dim3(QKV_N / 32, D_ / 32), dim3(32, 8)>>>(Wqkv, wqh, wql, D_, QKV_N);
    split_wT_kernel<<<dim3(D_ / 32, D_ / 32), dim3(32, 8)>>>(Wproj, wph, wpl, D_, D_);

    // 1) QKV projection -> bf16 hi/lo directly
    gemm_mma_kernel<true><<<dim3(QKV_N / 128, M_ / 128), 256, GM_SMEM>>>(
        xhi, xlo, wqh, wql, bqkv, nullptr, qkvh, qkvl, QKV_N, D_);

    // 2) causal flash attention (tensor cores) -> bf16 hi/lo
    attn_mma_kernel<<<dim3(L_ / 128, H_, B_), 256, AT_SMEM>>>(qkvh, qkvl, ahi, alo);

    // 3) output projection -> fp32 out
    gemm_mma_kernel<false><<<dim3(D_ / 128, M_ / 128), 256, GM_SMEM>>>(
        ahi, alo, wph, wpl, bproj, out, nullptr, nullptr, D_, D_);
}

// round 7
// speedup vs baseline: 2.5705x; 1.0003x over previous
#include <cuda_runtime.h>
#include <cuda_bf16.h>
#include <math_constants.h>
#include <cstdint>

// Problem constants
constexpr int B_  = 4;
constexpr int L_  = 2048;
constexpr int D_  = 1024;
constexpr int H_  = 16;
constexpr int HD_ = 64;
constexpr int M_  = B_ * L_;       // 8192
constexpr int QKV_N = 3 * D_;      // 3072

// ---------------------------------------------------------------------------
// Scratch (allocation-free -> __device__ globals)
// ---------------------------------------------------------------------------
__device__ __nv_bfloat16 g_xhi[(size_t)M_ * D_];
__device__ __nv_bfloat16 g_xlo[(size_t)M_ * D_];
__device__ __nv_bfloat16 g_qkvh[(size_t)M_ * QKV_N];   // qkv hi (bf16)
__device__ __nv_bfloat16 g_qkvl[(size_t)M_ * QKV_N];   // qkv lo
__device__ __nv_bfloat16 g_ahi[(size_t)M_ * D_];       // attn out hi
__device__ __nv_bfloat16 g_alo[(size_t)M_ * D_];       // attn out lo
__device__ __nv_bfloat16 g_wqh[(size_t)QKV_N * D_];    // Wqkv^T [N,K]
__device__ __nv_bfloat16 g_wql[(size_t)QKV_N * D_];
__device__ __nv_bfloat16 g_wph[(size_t)D_ * D_];       // Wproj^T [N,K]
__device__ __nv_bfloat16 g_wpl[(size_t)D_ * D_];

// ---------------------------------------------------------------------------
// PTX helpers
// ---------------------------------------------------------------------------
__device__ __forceinline__ uint32_t smem_u32(const void* p) {
    uint32_t a;
    asm("{ .reg .u64 t; cvta.to.shared.u64 t, %1; cvt.u32.u64 %0, t; }"
        : "=r"(a) : "l"(p));
    return a;
}
__device__ __forceinline__ void cpasync16(uint32_t saddr, const void* g) {
    asm volatile("cp.async.cg.shared.global [%0], [%1], 16;" :: "r"(saddr), "l"(g));
}
#define CP_COMMIT() asm volatile("cp.async.commit_group;" ::: "memory")
#define CP_WAIT(n)  asm volatile("cp.async.wait_group %0;" :: "n"(n) : "memory")

__device__ __forceinline__ void ldm_x4(uint32_t* r, uint32_t addr) {
    asm volatile("ldmatrix.sync.aligned.m8n8.x4.shared.b16 {%0,%1,%2,%3}, [%4];"
                 : "=r"(r[0]), "=r"(r[1]), "=r"(r[2]), "=r"(r[3]) : "r"(addr));
}
__device__ __forceinline__ void ldm_x4_t(uint32_t* r, uint32_t addr) {
    asm volatile("ldmatrix.sync.aligned.m8n8.x4.trans.shared.b16 {%0,%1,%2,%3}, [%4];"
                 : "=r"(r[0]), "=r"(r[1]), "=r"(r[2]), "=r"(r[3]) : "r"(addr));
}
// NOT volatile: pure register op, lets ptxas schedule/interleave
__device__ __forceinline__ void mma_bf16(float* c, const uint32_t* a,
                                         const uint32_t* b) {
    asm("mma.sync.aligned.m16n8k16.row.col.f32.bf16.bf16.f32 "
        "{%0,%1,%2,%3},{%4,%5,%6,%7},{%8,%9},{%0,%1,%2,%3};"
        : "+f"(c[0]), "+f"(c[1]), "+f"(c[2]), "+f"(c[3])
        : "r"(a[0]), "r"(a[1]), "r"(a[2]), "r"(a[3]), "r"(b[0]), "r"(b[1]));
}
// pack two fp32 into bf16x2 hi + residual lo
__device__ __forceinline__ void pack_hilo(float x, float y,
                                          uint32_t& hi, uint32_t& lo) {
    __nv_bfloat162 h2 = __floats2bfloat162_rn(x, y);
    float2 f2 = __bfloat1622float2(h2);
    __nv_bfloat162 l2 = __floats2bfloat162_rn(x - f2.x, y - f2.y);
    hi = *(uint32_t*)&h2;
    lo = *(uint32_t*)&l2;
}

// ---------------------------------------------------------------------------
// Split kernels
// ---------------------------------------------------------------------------
__global__ void split_a_kernel(const float* __restrict__ A,
                               __nv_bfloat16* __restrict__ Ah,
                               __nv_bfloat16* __restrict__ Al, int n4)
{
    int i = blockIdx.x * blockDim.x + threadIdx.x;
    if (i >= n4) return;
    float4 v = ((const float4*)A)[i];
    uint32_t h0, l0, h1, l1;
    pack_hilo(v.x, v.y, h0, l0);
    pack_hilo(v.z, v.w, h1, l1);
    ((uint32_t*)Ah)[2 * i]     = h0;
    ((uint32_t*)Ah)[2 * i + 1] = h1;
    ((uint32_t*)Al)[2 * i]     = l0;
    ((uint32_t*)Al)[2 * i + 1] = l1;
}

// W [K,N] fp32 -> Bh/Bl [N,K] bf16 (transpose + split)
__global__ void split_wT_kernel(const float* __restrict__ W,
                                __nv_bfloat16* __restrict__ Bh,
                                __nv_bfloat16* __restrict__ Bl, int K, int N)
{
    __shared__ float t[32][33];
    const int bx = blockIdx.x, by = blockIdx.y;
    const int tx = threadIdx.x, ty = threadIdx.y;
#pragma unroll
    for (int i = 0; i < 4; i++) {
        int k = by * 32 + ty + i * 8;
        t[ty + i * 8][tx] = W[(size_t)k * N + bx * 32 + tx];
    }
    __syncthreads();
#pragma unroll
    for (int i = 0; i < 4; i++) {
        int n = bx * 32 + ty + i * 8;
        int k = by * 32 + tx;
        float v = t[tx][ty + i * 8];
        __nv_bfloat16 h = __float2bfloat16_rn(v);
        Bh[(size_t)n * K + k] = h;
        Bl[(size_t)n * K + k] = __float2bfloat16_rn(v - __bfloat162float(h));
    }
}

// ---------------------------------------------------------------------------
// HMMA split-bf16 GEMM. SPLIT_OUT: write bf16 hi/lo instead of fp32.
// Pass-major MMA order: accumulator reuse distance 16 (was 1).
// ---------------------------------------------------------------------------
constexpr int GP = 40;
constexpr int GBUF = 128 * GP * 2;
constexpr int GSTAGE = 4 * GBUF;
constexpr size_t GM_SMEM = 2 * GSTAGE;     // 81920 B

template <bool SPLIT_OUT>
__global__ void __launch_bounds__(256, 1) gemm_mma_kernel(
    const __nv_bfloat16* __restrict__ Ah, const __nv_bfloat16* __restrict__ Al,
    const __nv_bfloat16* __restrict__ Bh, const __nv_bfloat16* __restrict__ Bl,
    const float* __restrict__ bias, float* __restrict__ C,
    __nv_bfloat16* __restrict__ Ch, __nv_bfloat16* __restrict__ Cl,
    int N, int K)
{
    extern __shared__ char smem[];
    const uint32_t sb = smem_u32(smem);
    const int tid  = threadIdx.x;
    const int wid  = tid >> 5;
    const int lane = tid & 31;
    const int warp_m = wid >> 2;
    const int warp_n = wid & 3;
    const int row0 = blockIdx.y * 128;
    const int col0 = blockIdx.x * 128;

    float acc[4][4][4];
#pragma unroll
    for (int mt = 0; mt < 4; mt++)
#pragma unroll
        for (int nt = 0; nt < 4; nt++)
#pragma unroll
            for (int q = 0; q < 4; q++) acc[mt][nt][q] = 0.f;

    const int nChunks = K >> 5;
    const int lr0 = tid >> 2;
    const int lc  = (tid & 3) * 8;

    auto load_stage = [&](int s, int c) {
        const int k0 = c << 5;
        const uint32_t st = sb + s * GSTAGE;
#pragma unroll
        for (int i = 0; i < 2; i++) {
            const int r = lr0 + i * 64;
            const uint32_t so = r * (GP * 2) + lc * 2;
            const size_t ga = (size_t)(row0 + r) * K + k0 + lc;
            const size_t gb = (size_t)(col0 + r) * K + k0 + lc;
            cpasync16(st + 0 * GBUF + so, Ah + ga);
            cpasync16(st + 1 * GBUF + so, Al + ga);
            cpasync16(st + 2 * GBUF + so, Bh + gb);
            cpasync16(st + 3 * GBUF + so, Bl + gb);
        }
    };

    load_stage(0, 0);
    CP_COMMIT();

    const int arow  = warp_m * 64 + (lane & 15);
    const int acolb = ((lane >> 4) & 1) * 16;
    const int bnrow = warp_n * 32 + (lane & 7) + ((lane >> 4) & 1) * 8;
    const int bcolb = ((lane >> 3) & 1) * 16;

    for (int c = 0; c < nChunks; c++) {
        const int cur = c & 1;
        if (c + 1 < nChunks) {
            load_stage(1 - cur, c + 1);
            CP_COMMIT();
            CP_WAIT(1);
        } else {
            CP_WAIT(0);
        }
        __syncthreads();

        const uint32_t st  = sb + cur * GSTAGE;
        const uint32_t sAh = st;
        const uint32_t sAl = st + GBUF;
        const uint32_t sBh = st + 2 * GBUF;
        const uint32_t sBl = st + 3 * GBUF;

#pragma unroll
        for (int ks = 0; ks < 2; ks++) {
            const int kb = ks * 32;
            uint32_t ah[4][4], al[4][4], bh[4][2], bl[4][2];
#pragma unroll
            for (int mt = 0; mt < 4; mt++) {
                const uint32_t ro = (uint32_t)(arow + mt * 16) * (GP * 2) + acolb + kb;
                ldm_x4(ah[mt], sAh + ro);
                ldm_x4(al[mt], sAl + ro);
            }
#pragma unroll
            for (int np = 0; np < 2; np++) {
                const uint32_t ro = (uint32_t)(bnrow + np * 16) * (GP * 2) + bcolb + kb;
                uint32_t t0[4], t1[4];
                ldm_x4(t0, sBh + ro);
                ldm_x4(t1, sBl + ro);
                bh[2 * np][0] = t0[0]; bh[2 * np][1] = t0[1];
                bh[2 * np + 1][0] = t0[2]; bh[2 * np + 1][1] = t0[3];
                bl[2 * np][0] = t1[0]; bl[2 * np][1] = t1[1];
                bl[2 * np + 1][0] = t1[2]; bl[2 * np + 1][1] = t1[3];
            }
            // pass-major: 16 independent MMAs between accumulator reuses
#pragma unroll
            for (int mt = 0; mt < 4; mt++)
#pragma unroll
                for (int nt = 0; nt < 4; nt++)
                    mma_bf16(acc[mt][nt], ah[mt], bh[nt]);
#pragma unroll
            for (int mt = 0; mt < 4; mt++)
#pragma unroll
                for (int nt = 0; nt < 4; nt++)
                    mma_bf16(acc[mt][nt], ah[mt], bl[nt]);
#pragma unroll
            for (int mt = 0; mt < 4; mt++)
#pragma unroll
                for (int nt = 0; nt < 4; nt++)
                    mma_bf16(acc[mt][nt], al[mt], bh[nt]);
        }
        __syncthreads();
    }

    const int g  = lane >> 2;
    const int tc = (lane & 3) * 2;
#pragma unroll
    for (int nt = 0; nt < 4; nt++) {
        const int cg = col0 + warp_n * 32 + nt * 8 + tc;
        const float bx = bias[cg];
        const float by = bias[cg + 1];
#pragma unroll
        for (int mt = 0; mt < 4; mt++) {
            const int rg = row0 + warp_m * 64 + mt * 16 + g;
            float v00 = acc[mt][nt][0] + bx, v01 = acc[mt][nt][1] + by;
            float v10 = acc[mt][nt][2] + bx, v11 = acc[mt][nt][3] + by;
            if (SPLIT_OUT) {
                uint32_t h0, l0, h1, l1;
                pack_hilo(v00, v01, h0, l0);
                pack_hilo(v10, v11, h1, l1);
                *(uint32_t*)(Ch + (size_t)rg * N + cg)       = h0;
                *(uint32_t*)(Cl + (size_t)rg * N + cg)       = l0;
                *(uint32_t*)(Ch + (size_t)(rg + 8) * N + cg) = h1;
                *(uint32_t*)(Cl + (size_t)(rg + 8) * N + cg) = l1;
            } else {
                float2 a0; a0.x = v00; a0.y = v01;
                float2 a1; a1.x = v10; a1.y = v11;
                *(float2*)(C + (size_t)rg * N + cg)       = a0;
                *(float2*)(C + (size_t)(rg + 8) * N + cg) = a1;
            }
        }
    }
}

// ---------------------------------------------------------------------------
// Tensor-core flash attention (causal). CTA = 128 q-rows x (b,h). 8 warps.
// K/V tiles of 64 keys, double-buffered cp.async.
// S = QhKh+QhKl+QlKh ; PV = PhVh+PhVl+PlVh ; fp32 accum throughout.
// Pass-major MMA order: accumulator reuse distance 8 (was 1).
// ---------------------------------------------------------------------------
constexpr int APB      = 144;               // smem pitch bytes (72 bf16)
constexpr int AT_QB    = 128 * APB;         // 18432 per Q tensor
constexpr int AT_KVT   = 64 * APB;          // 9216 per K/V tensor tile
constexpr int AT_STAGE = 4 * AT_KVT;        // 36864
constexpr size_t AT_SMEM = 2 * (size_t)AT_QB + 2 * (size_t)AT_STAGE;  // 110592

__global__ void __launch_bounds__(256, 1) attn_mma_kernel(
    const __nv_bfloat16* __restrict__ qkvh,
    const __nv_bfloat16* __restrict__ qkvl,
    __nv_bfloat16* __restrict__ outh,
    __nv_bfloat16* __restrict__ outl)
{
    extern __shared__ char smem[];
    const uint32_t sb = smem_u32(smem);
    const uint32_t sQh = sb;
    const uint32_t sQl = sb + AT_QB;
    const uint32_t sS0 = sb + 2 * AT_QB;

    const int qb = blockIdx.x;              // q-tile (128 rows)
    const int h  = blockIdx.y;
    const int b  = blockIdx.z;
    const int tid  = threadIdx.x;
    const int wid  = tid >> 5;
    const int lane = tid & 31;

    const size_t qrow0 = (size_t)(b * L_ + qb * 128);

    // ---- Q hi/lo -> smem ----
#pragma unroll
    for (int i = 0; i < 4; i++) {
        const int id = i * 256 + tid;
        const int r = id >> 3, s = id & 7;
        const size_t g = (qrow0 + r) * QKV_N + h * HD_ + s * 8;
        const uint32_t so = r * APB + s * 16;
        cpasync16(sQh + so, qkvh + g);
        cpasync16(sQl + so, qkvl + g);
    }
    CP_COMMIT();

    const int nkt = 2 * qb + 2;

    auto load_kv = [&](int buf, int kt) {
        const uint32_t st = sS0 + buf * AT_STAGE;
        const size_t krow0 = (size_t)(b * L_ + kt * 64);
#pragma unroll
        for (int i = 0; i < 2; i++) {
            const int id = i * 256 + tid;
            const int r = id >> 3, s = id & 7;
            const size_t gk = (krow0 + r) * QKV_N + D_ + h * HD_ + s * 8;
            const size_t gv = gk + D_;
            const uint32_t so = r * APB + s * 16;
            cpasync16(st + 0 * AT_KVT + so, qkvh + gk);
            cpasync16(st + 1 * AT_KVT + so, qkvl + gk);
            cpasync16(st + 2 * AT_KVT + so, qkvh + gv);
            cpasync16(st + 3 * AT_KVT + so, qkvl + gv);
        }
    };

    load_kv(0, 0);
    CP_COMMIT();

    // ---- Q fragments (after Q group done) ----
    CP_WAIT(1);
    __syncthreads();
    uint32_t qh[4][4], ql[4][4];
    {
        const uint32_t base = (uint32_t)(wid * 16 + (lane & 15)) * APB +
                              ((lane >> 4) & 1) * 16;
#pragma unroll
        for (int j = 0; j < 4; j++) {
            ldm_x4(qh[j], sQh + base + j * 32);
            ldm_x4(ql[j], sQl + base + j * 32);
        }
    }

    float o[8][4];
#pragma unroll
    for (int nt = 0; nt < 8; nt++)
#pragma unroll
        for (int q = 0; q < 4; q++) o[nt][q] = 0.f;
    float m0 = -CUDART_INF_F, m1 = -CUDART_INF_F;
    float l0 = 0.f, l1 = 0.f;

    const int row_r0 = qb * 128 + wid * 16 + (lane >> 2);  // global q row (and +8)
    const int ccol   = 2 * (lane & 3);
    constexpr float SCALE = 0.125f;
    constexpr float LOG2E = 1.44269504f;

    for (int kt = 0; kt < nkt; kt++) {
        const int buf = kt & 1;
        if (kt + 1 < nkt) {
            load_kv(1 - buf, kt + 1);
            CP_COMMIT();
            CP_WAIT(1);
        } else {
            CP_WAIT(0);
        }
        __syncthreads();

        const uint32_t st  = sS0 + buf * AT_STAGE;
        const uint32_t sKh = st;
        const uint32_t sKl = st + AT_KVT;
        const uint32_t sVh = st + 2 * AT_KVT;
        const uint32_t sVl = st + 3 * AT_KVT;

        // ---- S = Q K^T (3 split passes, pass-major) ----
        float s[8][4];
#pragma unroll
        for (int nt = 0; nt < 8; nt++)
#pragma unroll
            for (int q = 0; q < 4; q++) s[nt][q] = 0.f;

        const uint32_t kbase = (uint32_t)((lane & 7) + ((lane >> 4) & 1) * 8) * APB +
                               ((lane >> 3) & 1) * 16;
#pragma unroll
        for (int j = 0; j < 4; j++) {
            uint32_t kh[8][2], kl[8][2];
#pragma unroll
            for (int np = 0; np < 4; np++) {
                const uint32_t ro = kbase + (uint32_t)(np * 16) * APB + j * 32;
                uint32_t t0[4], t1[4];
                ldm_x4(t0, sKh + ro);
                ldm_x4(t1, sKl + ro);
                kh[2 * np][0] = t0[0]; kh[2 * np][1] = t0[1];
                kh[2 * np + 1][0] = t0[2]; kh[2 * np + 1][1] = t0[3];
                kl[2 * np][0] = t1[0]; kl[2 * np][1] = t1[1];
                kl[2 * np + 1][0] = t1[2]; kl[2 * np + 1][1] = t1[3];
            }
#pragma unroll
            for (int nt = 0; nt < 8; nt++)
                mma_bf16(s[nt], qh[j], kh[nt]);
#pragma unroll
            for (int nt = 0; nt < 8; nt++)
                mma_bf16(s[nt], qh[j], kl[nt]);
#pragma unroll
            for (int nt = 0; nt < 8; nt++)
                mma_bf16(s[nt], ql[j], kh[nt]);
        }

        // ---- scale + causal mask ----
#pragma unroll
        for (int nt = 0; nt < 8; nt++)
#pragma unroll
            for (int q = 0; q < 4; q++) s[nt][q] *= SCALE;

        if (kt >= 2 * qb) {
#pragma unroll
            for (int nt = 0; nt < 8; nt++) {
                const int col = kt * 64 + nt * 8 + ccol;
                if (col > row_r0)         s[nt][0] = -CUDART_INF_F;
                if (col + 1 > row_r0)     s[nt][1] = -CUDART_INF_F;
                if (col > row_r0 + 8)     s[nt][2] = -CUDART_INF_F;
                if (col + 1 > row_r0 + 8) s[nt][3] = -CUDART_INF_F;
            }
        }

        // ---- online softmax ----
        float tm0 = -CUDART_INF_F, tm1 = -CUDART_INF_F;
#pragma unroll
        for (int nt = 0; nt < 8; nt++) {
            tm0 = fmaxf(tm0, fmaxf(s[nt][0], s[nt][1]));
            tm1 = fmaxf(tm1, fmaxf(s[nt][2], s[nt][3]));
        }
        tm0 = fmaxf(tm0, __shfl_xor_sync(0xffffffffu, tm0, 1));
        tm0 = fmaxf(tm0, __shfl_xor_sync(0xffffffffu, tm0, 2));
        tm1 = fmaxf(tm1, __shfl_xor_sync(0xffffffffu, tm1, 1));
        tm1 = fmaxf(tm1, __shfl_xor_sync(0xffffffffu, tm1, 2));

        const float mn0 = fmaxf(m0, tm0);
        const float mn1 = fmaxf(m1, tm1);
        const float a0 = exp2f((m0 - mn0) * LOG2E);
        const float a1 = exp2f((m1 - mn1) * LOG2E);
        m0 = mn0; m1 = mn1;

        float rs0 = 0.f, rs1 = 0.f;
#pragma unroll
        for (int nt = 0; nt < 8; nt++) {
            float p0 = exp2f((s[nt][0] - mn0) * LOG2E);
            float p1 = exp2f((s[nt][1] - mn0) * LOG2E);
            float p2 = exp2f((s[nt][2] - mn1) * LOG2E);
            float p3 = exp2f((s[nt][3] - mn1) * LOG2E);
            s[nt][0] = p0; s[nt][1] = p1; s[nt][2] = p2; s[nt][3] = p3;
            rs0 += p0 + p1;
            rs1 += p2 + p3;
        }
        rs0 += __shfl_xor_sync(0xffffffffu, rs0, 1);
        rs0 += __shfl_xor_sync(0xffffffffu, rs0, 2);
        rs1 += __shfl_xor_sync(0xffffffffu, rs1, 1);
        rs1 += __shfl_xor_sync(0xffffffffu, rs1, 2);
        l0 = a0 * l0 + rs0;
        l1 = a1 * l1 + rs1;

#pragma unroll
        for (int nt = 0; nt < 8; nt++) {
            o[nt][0] *= a0; o[nt][1] *= a0;
            o[nt][2] *= a1; o[nt][3] *= a1;
        }

        // ---- pack P (C-frag -> A-frag identity) ----
        uint32_t ph[4][4], pl[4][4];
#pragma unroll
        for (int j = 0; j < 4; j++) {
            pack_hilo(s[2 * j][0],     s[2 * j][1],     ph[j][0], pl[j][0]);
            pack_hilo(s[2 * j][2],     s[2 * j][3],     ph[j][1], pl[j][1]);
            pack_hilo(s[2 * j + 1][0], s[2 * j + 1][1], ph[j][2], pl[j][2]);
            pack_hilo(s[2 * j + 1][2], s[2 * j + 1][3], ph[j][3], pl[j][3]);
        }

        // ---- O += P V (3 split passes, pass-major); V via ldmatrix.trans ----
        const int vmat = lane >> 3;
        const uint32_t vrowb = (uint32_t)((vmat & 1) * 8 + (lane & 7)) * APB +
                               (vmat >> 1) * 16;
#pragma unroll
        for (int j = 0; j < 4; j++) {
            uint32_t vh[8][2], vl[8][2];
#pragma unroll
            for (int pp = 0; pp < 4; pp++) {
                const uint32_t ro = vrowb + (uint32_t)(j * 16) * APB + pp * 32;
                uint32_t t0[4], t1[4];
                ldm_x4_t(t0, sVh + ro);
                ldm_x4_t(t1, sVl + ro);
                vh[2 * pp][0] = t0[0]; vh[2 * pp][1] = t0[1];
                vh[2 * pp + 1][0] = t0[2]; vh[2 * pp + 1][1] = t0[3];
                vl[2 * pp][0] = t1[0]; vl[2 * pp][1] = t1[1];
                vl[2 * pp + 1][0] = t1[2]; vl[2 * pp + 1][1] = t1[3];
            }
#pragma unroll
            for (int nt = 0; nt < 8; nt++)
                mma_bf16(o[nt], ph[j], vh[nt]);
#pragma unroll
            for (int nt = 0; nt < 8; nt++)
                mma_bf16(o[nt], ph[j], vl[nt]);
#pragma unroll
            for (int nt = 0; nt < 8; nt++)
                mma_bf16(o[nt], pl[j], vh[nt]);
        }
        __syncthreads();
    }

    // ---- finalize: /l, split hi/lo, store ----
    const float inv0 = 1.0f / l0;
    const float inv1 = 1.0f / l1;
    const size_t grow0 = qrow0 + wid * 16 + (lane >> 2);
#pragma unroll
    for (int nt = 0; nt < 8; nt++) {
        const int col = h * HD_ + nt * 8 + ccol;
        uint32_t h0, lo0, h1, lo1;
        pack_hilo(o[nt][0] * inv0, o[nt][1] * inv0, h0, lo0);
        pack_hilo(o[nt][2] * inv1, o[nt][3] * inv1, h1, lo1);
        *(uint32_t*)(outh + grow0 * D_ + col)       = h0;
        *(uint32_t*)(outl + grow0 * D_ + col)       = lo0;
        *(uint32_t*)(outh + (grow0 + 8) * D_ + col) = h1;
        *(uint32_t*)(outl + (grow0 + 8) * D_ + col) = lo1;
    }
}

// ----------------------------------------------------------------------------
// Launch
// ----------------------------------------------------------------------------
extern "C" void kernel_launch(void* const* d_in, const int* in_sizes, int n_in,
                              void* d_out, int out_size)
{
    const float* x     = (const float*)d_in[0];
    const float* Wqkv  = (const float*)d_in[1];
    const float* bqkv  = (const float*)d_in[2];
    const float* Wproj = (const float*)d_in[3];
    const float* bproj = (const float*)d_in[4];
    float* out = (float*)d_out;

    __nv_bfloat16 *xhi, *xlo, *qkvh, *qkvl, *ahi, *alo, *wqh, *wql, *wph, *wpl;
    cudaGetSymbolAddress((void**)&xhi, g_xhi);
    cudaGetSymbolAddress((void**)&xlo, g_xlo);
    cudaGetSymbolAddress((void**)&qkvh, g_qkvh);
    cudaGetSymbolAddress((void**)&qkvl, g_qkvl);
    cudaGetSymbolAddress((void**)&ahi, g_ahi);
    cudaGetSymbolAddress((void**)&alo, g_alo);
    cudaGetSymbolAddress((void**)&wqh, g_wqh);
    cudaGetSymbolAddress((void**)&wql, g_wql);
    cudaGetSymbolAddress((void**)&wph, g_wph);
    cudaGetSymbolAddress((void**)&wpl, g_wpl);

    static bool attr_set = false;
    if (!attr_set) {
        cudaFuncSetAttribute(gemm_mma_kernel<true>,
                             cudaFuncAttributeMaxDynamicSharedMemorySize,
                             (int)GM_SMEM);
        cudaFuncSetAttribute(gemm_mma_kernel<false>,
                             cudaFuncAttributeMaxDynamicSharedMemorySize,
                             (int)GM_SMEM);
        cudaFuncSetAttribute(attn_mma_kernel,
                             cudaFuncAttributeMaxDynamicSharedMemorySize,
                             (int)AT_SMEM);
        attr_set = true;
    }

    const int n4x = M_ * D_ / 4;

    // prep: splits
    split_a_kernel<<<(n4x + 255) / 256, 256>>>(x, xhi, xlo, n4x);
    split_wT_kernel<<<dim3(QKV_N / 32, D_ / 32), dim3(32, 8)>>>(Wqkv, wqh, wql, D_, QKV_N);
    split_wT_kernel<<<dim3(D_ / 32, D_ / 32), dim3(32, 8)>>>(Wproj, wph, wpl, D_, D_);

    // 1) QKV projection -> bf16 hi/lo directly
    gemm_mma_kernel<true><<<dim3(QKV_N / 128, M_ / 128), 256, GM_SMEM>>>(
        xhi, xlo, wqh, wql, bqkv, nullptr, qkvh, qkvl, QKV_N, D_);

    // 2) causal flash attention (tensor cores) -> bf16 hi/lo
    attn_mma_kernel<<<dim3(L_ / 128, H_, B_), 256, AT_SMEM>>>(qkvh, qkvl, ahi, alo);

    // 3) output projection -> fp32 out
    gemm_mma_kernel<false><<<dim3(D_ / 128, M_ / 128), 256, GM_SMEM>>>(
        ahi, alo, wph, wpl, bproj, out, nullptr, nullptr, D_, D_);
}

// round 8
// speedup vs baseline: 2.8894x; 1.1241x over previous
#include <cuda_runtime.h>
#include <cuda_bf16.h>
#include <math_constants.h>
#include <cstdint>

// Problem constants
constexpr int B_  = 4;
constexpr int L_  = 2048;
constexpr int D_  = 1024;
constexpr int H_  = 16;
constexpr int HD_ = 64;
constexpr int M_  = B_ * L_;       // 8192
constexpr int QKV_N = 3 * D_;      // 3072

// ---------------------------------------------------------------------------
// Scratch (allocation-free -> __device__ globals)
// ---------------------------------------------------------------------------
__device__ __nv_bfloat16 g_xhi[(size_t)M_ * D_];
__device__ __nv_bfloat16 g_xlo[(size_t)M_ * D_];
__device__ __nv_bfloat16 g_qkvh[(size_t)M_ * QKV_N];   // qkv hi (bf16)
__device__ __nv_bfloat16 g_qkvl[(size_t)M_ * QKV_N];   // qkv lo
__device__ __nv_bfloat16 g_ahi[(size_t)M_ * D_];       // attn out hi
__device__ __nv_bfloat16 g_alo[(size_t)M_ * D_];       // attn out lo
__device__ __nv_bfloat16 g_wqh[(size_t)QKV_N * D_];    // Wqkv^T [N,K]
__device__ __nv_bfloat16 g_wql[(size_t)QKV_N * D_];
__device__ __nv_bfloat16 g_wph[(size_t)D_ * D_];       // Wproj^T [N,K]
__device__ __nv_bfloat16 g_wpl[(size_t)D_ * D_];

// ---------------------------------------------------------------------------
// PTX helpers
// ---------------------------------------------------------------------------
__device__ __forceinline__ uint32_t smem_u32(const void* p) {
    uint32_t a;
    asm("{ .reg .u64 t; cvta.to.shared.u64 t, %1; cvt.u32.u64 %0, t; }"
        : "=r"(a) : "l"(p));
    return a;
}
__device__ __forceinline__ void cpasync16(uint32_t saddr, const void* g) {
    asm volatile("cp.async.cg.shared.global [%0], [%1], 16;" :: "r"(saddr), "l"(g));
}
#define CP_COMMIT() asm volatile("cp.async.commit_group;" ::: "memory")
#define CP_WAIT(n)  asm volatile("cp.async.wait_group %0;" :: "n"(n) : "memory")

__device__ __forceinline__ void ldm_x4(uint32_t* r, uint32_t addr) {
    asm volatile("ldmatrix.sync.aligned.m8n8.x4.shared.b16 {%0,%1,%2,%3}, [%4];"
                 : "=r"(r[0]), "=r"(r[1]), "=r"(r[2]), "=r"(r[3]) : "r"(addr));
}
__device__ __forceinline__ void ldm_x4_t(uint32_t* r, uint32_t addr) {
    asm volatile("ldmatrix.sync.aligned.m8n8.x4.trans.shared.b16 {%0,%1,%2,%3}, [%4];"
                 : "=r"(r[0]), "=r"(r[1]), "=r"(r[2]), "=r"(r[3]) : "r"(addr));
}
// not volatile: pure register op, ptxas may schedule freely
__device__ __forceinline__ void mma_bf16(float* c, const uint32_t* a,
                                         const uint32_t* b) {
    asm("mma.sync.aligned.m16n8k16.row.col.f32.bf16.bf16.f32 "
        "{%0,%1,%2,%3},{%4,%5,%6,%7},{%8,%9},{%0,%1,%2,%3};"
        : "+f"(c[0]), "+f"(c[1]), "+f"(c[2]), "+f"(c[3])
        : "r"(a[0]), "r"(a[1]), "r"(a[2]), "r"(a[3]), "r"(b[0]), "r"(b[1]));
}
// pack two fp32 into bf16x2 hi + residual lo
__device__ __forceinline__ void pack_hilo(float x, float y,
                                          uint32_t& hi, uint32_t& lo) {
    __nv_bfloat162 h2 = __floats2bfloat162_rn(x, y);
    float2 f2 = __bfloat1622float2(h2);
    __nv_bfloat162 l2 = __floats2bfloat162_rn(x - f2.x, y - f2.y);
    hi = *(uint32_t*)&h2;
    lo = *(uint32_t*)&l2;
}

// ---------------------------------------------------------------------------
// Split kernels
// ---------------------------------------------------------------------------
__global__ void split_a_kernel(const float* __restrict__ A,
                               __nv_bfloat16* __restrict__ Ah,
                               __nv_bfloat16* __restrict__ Al, int n4)
{
    int i = blockIdx.x * blockDim.x + threadIdx.x;
    if (i >= n4) return;
    float4 v = ((const float4*)A)[i];
    uint32_t h0, l0, h1, l1;
    pack_hilo(v.x, v.y, h0, l0);
    pack_hilo(v.z, v.w, h1, l1);
    ((uint32_t*)Ah)[2 * i]     = h0;
    ((uint32_t*)Ah)[2 * i + 1] = h1;
    ((uint32_t*)Al)[2 * i]     = l0;
    ((uint32_t*)Al)[2 * i + 1] = l1;
}

// W [K,N] fp32 -> Bh/Bl [N,K] bf16 (transpose + split)
__global__ void split_wT_kernel(const float* __restrict__ W,
                                __nv_bfloat16* __restrict__ Bh,
                                __nv_bfloat16* __restrict__ Bl, int K, int N)
{
    __shared__ float t[32][33];
    const int bx = blockIdx.x, by = blockIdx.y;
    const int tx = threadIdx.x, ty = threadIdx.y;
#pragma unroll
    for (int i = 0; i < 4; i++) {
        int k = by * 32 + ty + i * 8;
        t[ty + i * 8][tx] = W[(size_t)k * N + bx * 32 + tx];
    }
    __syncthreads();
#pragma unroll
    for (int i = 0; i < 4; i++) {
        int n = bx * 32 + ty + i * 8;
        int k = by * 32 + tx;
        float v = t[tx][ty + i * 8];
        __nv_bfloat16 h = __float2bfloat16_rn(v);
        Bh[(size_t)n * K + k] = h;
        Bl[(size_t)n * K + k] = __float2bfloat16_rn(v - __bfloat162float(h));
    }
}

// ---------------------------------------------------------------------------
// HMMA split-bf16 GEMM. SPLIT_OUT: write bf16 hi/lo instead of fp32.
// 2 CTAs/SM (register-lean mainloop: B frags resident, A frags streamed).
// ---------------------------------------------------------------------------
constexpr int GP = 40;
constexpr int GBUF = 128 * GP * 2;
constexpr int GSTAGE = 4 * GBUF;
constexpr size_t GM_SMEM = 2 * GSTAGE;     // 81920 B

template <bool SPLIT_OUT>
__global__ void __launch_bounds__(256, 2) gemm_mma_kernel(
    const __nv_bfloat16* __restrict__ Ah, const __nv_bfloat16* __restrict__ Al,
    const __nv_bfloat16* __restrict__ Bh, const __nv_bfloat16* __restrict__ Bl,
    const float* __restrict__ bias, float* __restrict__ C,
    __nv_bfloat16* __restrict__ Ch, __nv_bfloat16* __restrict__ Cl,
    int N, int K)
{
    extern __shared__ char smem[];
    const uint32_t sb = smem_u32(smem);
    const int tid  = threadIdx.x;
    const int wid  = tid >> 5;
    const int lane = tid & 31;
    const int warp_m = wid >> 2;
    const int warp_n = wid & 3;
    const int row0 = blockIdx.y * 128;
    const int col0 = blockIdx.x * 128;

    float acc[4][4][4];
#pragma unroll
    for (int mt = 0; mt < 4; mt++)
#pragma unroll
        for (int nt = 0; nt < 4; nt++)
#pragma unroll
            for (int q = 0; q < 4; q++) acc[mt][nt][q] = 0.f;

    const int nChunks = K >> 5;
    const int lr0 = tid >> 2;
    const int lc  = (tid & 3) * 8;

    auto load_stage = [&](int s, int c) {
        const int k0 = c << 5;
        const uint32_t st = sb + s * GSTAGE;
#pragma unroll
        for (int i = 0; i < 2; i++) {
            const int r = lr0 + i * 64;
            const uint32_t so = r * (GP * 2) + lc * 2;
            const size_t ga = (size_t)(row0 + r) * K + k0 + lc;
            const size_t gb = (size_t)(col0 + r) * K + k0 + lc;
            cpasync16(st + 0 * GBUF + so, Ah + ga);
            cpasync16(st + 1 * GBUF + so, Al + ga);
            cpasync16(st + 2 * GBUF + so, Bh + gb);
            cpasync16(st + 3 * GBUF + so, Bl + gb);
        }
    };

    load_stage(0, 0);
    CP_COMMIT();

    const int arow  = warp_m * 64 + (lane & 15);
    const int acolb = ((lane >> 4) & 1) * 16;
    const int bnrow = warp_n * 32 + (lane & 7) + ((lane >> 4) & 1) * 8;
    const int bcolb = ((lane >> 3) & 1) * 16;

    for (int c = 0; c < nChunks; c++) {
        const int cur = c & 1;
        if (c + 1 < nChunks) {
            load_stage(1 - cur, c + 1);
            CP_COMMIT();
            CP_WAIT(1);
        } else {
            CP_WAIT(0);
        }
        __syncthreads();

        const uint32_t st  = sb + cur * GSTAGE;
        const uint32_t sAh = st;
        const uint32_t sAl = st + GBUF;
        const uint32_t sBh = st + 2 * GBUF;
        const uint32_t sBl = st + 3 * GBUF;

#pragma unroll
        for (int ks = 0; ks < 2; ks++) {
            const int kb = ks * 32;
            // B fragments resident for this k16 step (16 regs)
            uint32_t bh[4][2], bl[4][2];
#pragma unroll
            for (int np = 0; np < 2; np++) {
                const uint32_t ro = (uint32_t)(bnrow + np * 16) * (GP * 2) + bcolb + kb;
                uint32_t t0[4], t1[4];
                ldm_x4(t0, sBh + ro);
                ldm_x4(t1, sBl + ro);
                bh[2 * np][0] = t0[0]; bh[2 * np][1] = t0[1];
                bh[2 * np + 1][0] = t0[2]; bh[2 * np + 1][1] = t0[3];
                bl[2 * np][0] = t1[0]; bl[2 * np][1] = t1[1];
                bl[2 * np + 1][0] = t1[2]; bl[2 * np + 1][1] = t1[3];
            }
            // A fragments streamed per mt (8 regs live) — register-lean
#pragma unroll
            for (int mt = 0; mt < 4; mt++) {
                const uint32_t ro = (uint32_t)(arow + mt * 16) * (GP * 2) + acolb + kb;
                uint32_t ah[4], al[4];
                ldm_x4(ah, sAh + ro);
                ldm_x4(al, sAl + ro);
#pragma unroll
                for (int nt = 0; nt < 4; nt++)
                    mma_bf16(acc[mt][nt], ah, bh[nt]);
#pragma unroll
                for (int nt = 0; nt < 4; nt++)
                    mma_bf16(acc[mt][nt], ah, bl[nt]);
#pragma unroll
                for (int nt = 0; nt < 4; nt++)
                    mma_bf16(acc[mt][nt], al, bh[nt]);
            }
        }
        __syncthreads();
    }

    const int g  = lane >> 2;
    const int tc = (lane & 3) * 2;
#pragma unroll
    for (int nt = 0; nt < 4; nt++) {
        const int cg = col0 + warp_n * 32 + nt * 8 + tc;
        const float bx = bias[cg];
        const float by = bias[cg + 1];
#pragma unroll
        for (int mt = 0; mt < 4; mt++) {
            const int rg = row0 + warp_m * 64 + mt * 16 + g;
            float v00 = acc[mt][nt][0] + bx, v01 = acc[mt][nt][1] + by;
            float v10 = acc[mt][nt][2] + bx, v11 = acc[mt][nt][3] + by;
            if (SPLIT_OUT) {
                uint32_t h0, l0, h1, l1;
                pack_hilo(v00, v01, h0, l0);
                pack_hilo(v10, v11, h1, l1);
                *(uint32_t*)(Ch + (size_t)rg * N + cg)       = h0;
                *(uint32_t*)(Cl + (size_t)rg * N + cg)       = l0;
                *(uint32_t*)(Ch + (size_t)(rg + 8) * N + cg) = h1;
                *(uint32_t*)(Cl + (size_t)(rg + 8) * N + cg) = l1;
            } else {
                float2 a0; a0.x = v00; a0.y = v01;
                float2 a1; a1.x = v10; a1.y = v11;
                *(float2*)(C + (size_t)rg * N + cg)       = a0;
                *(float2*)(C + (size_t)(rg + 8) * N + cg) = a1;
            }
        }
    }
}

// ---------------------------------------------------------------------------
// Tensor-core flash attention (causal). CTA = 128 q-rows x (b,h). 8 warps.
// K/V tiles of 64 keys, double-buffered cp.async. (unchanged from round 6)
// ---------------------------------------------------------------------------
constexpr int APB      = 144;               // smem pitch bytes (72 bf16)
constexpr int AT_QB    = 128 * APB;         // 18432 per Q tensor
constexpr int AT_KVT   = 64 * APB;          // 9216 per K/V tensor tile
constexpr int AT_STAGE = 4 * AT_KVT;        // 36864
constexpr size_t AT_SMEM = 2 * (size_t)AT_QB + 2 * (size_t)AT_STAGE;  // 110592

__global__ void __launch_bounds__(256, 1) attn_mma_kernel(
    const __nv_bfloat16* __restrict__ qkvh,
    const __nv_bfloat16* __restrict__ qkvl,
    __nv_bfloat16* __restrict__ outh,
    __nv_bfloat16* __restrict__ outl)
{
    extern __shared__ char smem[];
    const uint32_t sb = smem_u32(smem);
    const uint32_t sQh = sb;
    const uint32_t sQl = sb + AT_QB;
    const uint32_t sS0 = sb + 2 * AT_QB;

    const int qb = blockIdx.x;              // q-tile (128 rows)
    const int h  = blockIdx.y;
    const int b  = blockIdx.z;
    const int tid  = threadIdx.x;
    const int wid  = tid >> 5;
    const int lane = tid & 31;

    const size_t qrow0 = (size_t)(b * L_ + qb * 128);

    // ---- Q hi/lo -> smem ----
#pragma unroll
    for (int i = 0; i < 4; i++) {
        const int id = i * 256 + tid;
        const int r = id >> 3, s = id & 7;
        const size_t g = (qrow0 + r) * QKV_N + h * HD_ + s * 8;
        const uint32_t so = r * APB + s * 16;
        cpasync16(sQh + so, qkvh + g);
        cpasync16(sQl + so, qkvl + g);
    }
    CP_COMMIT();

    const int nkt = 2 * qb + 2;

    auto load_kv = [&](int buf, int kt) {
        const uint32_t st = sS0 + buf * AT_STAGE;
        const size_t krow0 = (size_t)(b * L_ + kt * 64);
#pragma unroll
        for (int i = 0; i < 2; i++) {
            const int id = i * 256 + tid;
            const int r = id >> 3, s = id & 7;
            const size_t gk = (krow0 + r) * QKV_N + D_ + h * HD_ + s * 8;
            const size_t gv = gk + D_;
            const uint32_t so = r * APB + s * 16;
            cpasync16(st + 0 * AT_KVT + so, qkvh + gk);
            cpasync16(st + 1 * AT_KVT + so, qkvl + gk);
            cpasync16(st + 2 * AT_KVT + so, qkvh + gv);
            cpasync16(st + 3 * AT_KVT + so, qkvl + gv);
        }
    };

    load_kv(0, 0);
    CP_COMMIT();

    // ---- Q fragments (after Q group done) ----
    CP_WAIT(1);
    __syncthreads();
    uint32_t qh[4][4], ql[4][4];
    {
        const uint32_t base = (uint32_t)(wid * 16 + (lane & 15)) * APB +
                              ((lane >> 4) & 1) * 16;
#pragma unroll
        for (int j = 0; j < 4; j++) {
            ldm_x4(qh[j], sQh + base + j * 32);
            ldm_x4(ql[j], sQl + base + j * 32);
        }
    }

    float o[8][4];
#pragma unroll
    for (int nt = 0; nt < 8; nt++)
#pragma unroll
        for (int q = 0; q < 4; q++) o[nt][q] = 0.f;
    float m0 = -CUDART_INF_F, m1 = -CUDART_INF_F;
    float l0 = 0.f, l1 = 0.f;

    const int row_r0 = qb * 128 + wid * 16 + (lane >> 2);  // global q row (and +8)
    const int ccol   = 2 * (lane & 3);
    constexpr float SCALE = 0.125f;
    constexpr float LOG2E = 1.44269504f;

    for (int kt = 0; kt < nkt; kt++) {
        const int buf = kt & 1;
        if (kt + 1 < nkt) {
            load_kv(1 - buf, kt + 1);
            CP_COMMIT();
            CP_WAIT(1);
        } else {
            CP_WAIT(0);
        }
        __syncthreads();

        const uint32_t st  = sS0 + buf * AT_STAGE;
        const uint32_t sKh = st;
        const uint32_t sKl = st + AT_KVT;
        const uint32_t sVh = st + 2 * AT_KVT;
        const uint32_t sVl = st + 3 * AT_KVT;

        // ---- S = Q K^T (3 split passes) ----
        float s[8][4];
#pragma unroll
        for (int nt = 0; nt < 8; nt++)
#pragma unroll
            for (int q = 0; q < 4; q++) s[nt][q] = 0.f;

        const uint32_t kbase = (uint32_t)((lane & 7) + ((lane >> 4) & 1) * 8) * APB +
                               ((lane >> 3) & 1) * 16;
#pragma unroll
        for (int j = 0; j < 4; j++) {
            uint32_t kh[8][2], kl[8][2];
#pragma unroll
            for (int np = 0; np < 4; np++) {
                const uint32_t ro = kbase + (uint32_t)(np * 16) * APB + j * 32;
                uint32_t t0[4], t1[4];
                ldm_x4(t0, sKh + ro);
                ldm_x4(t1, sKl + ro);
                kh[2 * np][0] = t0[0]; kh[2 * np][1] = t0[1];
                kh[2 * np + 1][0] = t0[2]; kh[2 * np + 1][1] = t0[3];
                kl[2 * np][0] = t1[0]; kl[2 * np][1] = t1[1];
                kl[2 * np + 1][0] = t1[2]; kl[2 * np + 1][1] = t1[3];
            }
#pragma unroll
            for (int nt = 0; nt < 8; nt++)
                mma_bf16(s[nt], qh[j], kh[nt]);
#pragma unroll
            for (int nt = 0; nt < 8; nt++)
                mma_bf16(s[nt], qh[j], kl[nt]);
#pragma unroll
            for (int nt = 0; nt < 8; nt++)
                mma_bf16(s[nt], ql[j], kh[nt]);
        }

        // ---- scale + causal mask ----
#pragma unroll
        for (int nt = 0; nt < 8; nt++)
#pragma unroll
            for (int q = 0; q < 4; q++) s[nt][q] *= SCALE;

        if (kt >= 2 * qb) {
#pragma unroll
            for (int nt = 0; nt < 8; nt++) {
                const int col = kt * 64 + nt * 8 + ccol;
                if (col > row_r0)         s[nt][0] = -CUDART_INF_F;
                if (col + 1 > row_r0)     s[nt][1] = -CUDART_INF_F;
                if (col > row_r0 + 8)     s[nt][2] = -CUDART_INF_F;
                if (col + 1 > row_r0 + 8) s[nt][3] = -CUDART_INF_F;
            }
        }

        // ---- online softmax ----
        float tm0 = -CUDART_INF_F, tm1 = -CUDART_INF_F;
#pragma unroll
        for (int nt = 0; nt < 8; nt++) {
            tm0 = fmaxf(tm0, fmaxf(s[nt][0], s[nt][1]));
            tm1 = fmaxf(tm1, fmaxf(s[nt][2], s[nt][3]));
        }
        tm0 = fmaxf(tm0, __shfl_xor_sync(0xffffffffu, tm0, 1));
        tm0 = fmaxf(tm0, __shfl_xor_sync(0xffffffffu, tm0, 2));
        tm1 = fmaxf(tm1, __shfl_xor_sync(0xffffffffu, tm1, 1));
        tm1 = fmaxf(tm1, __shfl_xor_sync(0xffffffffu, tm1, 2));

        const float mn0 = fmaxf(m0, tm0);
        const float mn1 = fmaxf(m1, tm1);
        const float a0 = exp2f((m0 - mn0) * LOG2E);
        const float a1 = exp2f((m1 - mn1) * LOG2E);
        m0 = mn0; m1 = mn1;

        float rs0 = 0.f, rs1 = 0.f;
#pragma unroll
        for (int nt = 0; nt < 8; nt++) {
            float p0 = exp2f((s[nt][0] - mn0) * LOG2E);
            float p1 = exp2f((s[nt][1] - mn0) * LOG2E);
            float p2 = exp2f((s[nt][2] - mn1) * LOG2E);
            float p3 = exp2f((s[nt][3] - mn1) * LOG2E);
            s[nt][0] = p0; s[nt][1] = p1; s[nt][2] = p2; s[nt][3] = p3;
            rs0 += p0 + p1;
            rs1 += p2 + p3;
        }
        rs0 += __shfl_xor_sync(0xffffffffu, rs0, 1);
        rs0 += __shfl_xor_sync(0xffffffffu, rs0, 2);
        rs1 += __shfl_xor_sync(0xffffffffu, rs1, 1);
        rs1 += __shfl_xor_sync(0xffffffffu, rs1, 2);
        l0 = a0 * l0 + rs0;
        l1 = a1 * l1 + rs1;

#pragma unroll
        for (int nt = 0; nt < 8; nt++) {
            o[nt][0] *= a0; o[nt][1] *= a0;
            o[nt][2] *= a1; o[nt][3] *= a1;
        }

        // ---- pack P (C-frag -> A-frag identity) ----
        uint32_t ph[4][4], pl[4][4];
#pragma unroll
        for (int j = 0; j < 4; j++) {
            pack_hilo(s[2 * j][0],     s[2 * j][1],     ph[j][0], pl[j][0]);
            pack_hilo(s[2 * j][2],     s[2 * j][3],     ph[j][1], pl[j][1]);
            pack_hilo(s[2 * j + 1][0], s[2 * j + 1][1], ph[j][2], pl[j][2]);
            pack_hilo(s[2 * j + 1][2], s[2 * j + 1][3], ph[j][3], pl[j][3]);
        }

        // ---- O += P V (3 split passes); V via ldmatrix.trans ----
        const int vmat = lane >> 3;
        const uint32_t vrowb = (uint32_t)((vmat & 1) * 8 + (lane & 7)) * APB +
                               (vmat >> 1) * 16;
#pragma unroll
        for (int j = 0; j < 4; j++) {
            uint32_t vh[8][2], vl[8][2];
#pragma unroll
            for (int pp = 0; pp < 4; pp++) {
                const uint32_t ro = vrowb + (uint32_t)(j * 16) * APB + pp * 32;
                uint32_t t0[4], t1[4];
                ldm_x4_t(t0, sVh + ro);
                ldm_x4_t(t1, sVl + ro);
                vh[2 * pp][0] = t0[0]; vh[2 * pp][1] = t0[1];
                vh[2 * pp + 1][0] = t0[2]; vh[2 * pp + 1][1] = t0[3];
                vl[2 * pp][0] = t1[0]; vl[2 * pp][1] = t1[1];
                vl[2 * pp + 1][0] = t1[2]; vl[2 * pp + 1][1] = t1[3];
            }
#pragma unroll
            for (int nt = 0; nt < 8; nt++)
                mma_bf16(o[nt], ph[j], vh[nt]);
#pragma unroll
            for (int nt = 0; nt < 8; nt++)
                mma_bf16(o[nt], ph[j], vl[nt]);
#pragma unroll
            for (int nt = 0; nt < 8; nt++)
                mma_bf16(o[nt], pl[j], vh[nt]);
        }
        __syncthreads();
    }

    // ---- finalize: /l, split hi/lo, store ----
    const float inv0 = 1.0f / l0;
    const float inv1 = 1.0f / l1;
    const size_t grow0 = qrow0 + wid * 16 + (lane >> 2);
#pragma unroll
    for (int nt = 0; nt < 8; nt++) {
        const int col = h * HD_ + nt * 8 + ccol;
        uint32_t h0, lo0, h1, lo1;
        pack_hilo(o[nt][0] * inv0, o[nt][1] * inv0, h0, lo0);
        pack_hilo(o[nt][2] * inv1, o[nt][3] * inv1, h1, lo1);
        *(uint32_t*)(outh + grow0 * D_ + col)       = h0;
        *(uint32_t*)(outl + grow0 * D_ + col)       = lo0;
        *(uint32_t*)(outh + (grow0 + 8) * D_ + col) = h1;
        *(uint32_t*)(outl + (grow0 + 8) * D_ + col) = lo1;
    }
}

// ----------------------------------------------------------------------------
// Launch
// ----------------------------------------------------------------------------
extern "C" void kernel_launch(void* const* d_in, const int* in_sizes, int n_in,
                              void* d_out, int out_size)
{
    const float* x     = (const float*)d_in[0];
    const float* Wqkv  = (const float*)d_in[1];
    const float* bqkv  = (const float*)d_in[2];
    const float* Wproj = (const float*)d_in[3];
    const float* bproj = (const float*)d_in[4];
    float* out = (float*)d_out;

    __nv_bfloat16 *xhi, *xlo, *qkvh, *qkvl, *ahi, *alo, *wqh, *wql, *wph, *wpl;
    cudaGetSymbolAddress((void**)&xhi, g_xhi);
    cudaGetSymbolAddress((void**)&xlo, g_xlo);
    cudaGetSymbolAddress((void**)&qkvh, g_qkvh);
    cudaGetSymbolAddress((void**)&qkvl, g_qkvl);
    cudaGetSymbolAddress((void**)&ahi, g_ahi);
    cudaGetSymbolAddress((void**)&alo, g_alo);
    cudaGetSymbolAddress((void**)&wqh, g_wqh);
    cudaGetSymbolAddress((void**)&wql, g_wql);
    cudaGetSymbolAddress((void**)&wph, g_wph);
    cudaGetSymbolAddress((void**)&wpl, g_wpl);

    static bool attr_set = false;
    if (!attr_set) {
        cudaFuncSetAttribute(gemm_mma_kernel<true>,
                             cudaFuncAttributeMaxDynamicSharedMemorySize,
                             (int)GM_SMEM);
        cudaFuncSetAttribute(gemm_mma_kernel<false>,
                             cudaFuncAttributeMaxDynamicSharedMemorySize,
                             (int)GM_SMEM);
        cudaFuncSetAttribute(attn_mma_kernel,
                             cudaFuncAttributeMaxDynamicSharedMemorySize,
                             (int)AT_SMEM);
        attr_set = true;
    }

    const int n4x = M_ * D_ / 4;

    // prep: splits
    split_a_kernel<<<(n4x + 255) / 256, 256>>>(x, xhi, xlo, n4x);
    split_wT_kernel<<<dim3(QKV_N / 32, D_ / 32), dim3(32, 8)>>>(Wqkv, wqh, wql, D_, QKV_N);
    split_wT_kernel<<<dim3(D_ / 32, D_ / 32), dim3(32, 8)>>>(Wproj, wph, wpl, D_, D_);

    // 1) QKV projection -> bf16 hi/lo directly
    gemm_mma_kernel<true><<<dim3(QKV_N / 128, M_ / 128), 256, GM_SMEM>>>(
        xhi, xlo, wqh, wql, bqkv, nullptr, qkvh, qkvl, QKV_N, D_);

    // 2) causal flash attention (tensor cores) -> bf16 hi/lo
    attn_mma_kernel<<<dim3(L_ / 128, H_, B_), 256, AT_SMEM>>>(qkvh, qkvl, ahi, alo);

    // 3) output projection -> fp32 out
    gemm_mma_kernel<false><<<dim3(D_ / 128, M_ / 128), 256, GM_SMEM>>>(
        ahi, alo, wph, wpl, bproj, out, nullptr, nullptr, D_, D_);
}

// round 9
// speedup vs baseline: 2.9540x; 1.0223x over previous
#include <cuda_runtime.h>
#include <cuda_bf16.h>
#include <math_constants.h>
#include <cstdint>

// Problem constants
constexpr int B_  = 4;
constexpr int L_  = 2048;
constexpr int D_  = 1024;
constexpr int H_  = 16;
constexpr int HD_ = 64;
constexpr int M_  = B_ * L_;       // 8192
constexpr int QKV_N = 3 * D_;      // 3072

// ---------------------------------------------------------------------------
// Scratch (allocation-free -> __device__ globals)
// ---------------------------------------------------------------------------
__device__ __nv_bfloat16 g_xhi[(size_t)M_ * D_];
__device__ __nv_bfloat16 g_xlo[(size_t)M_ * D_];
__device__ __nv_bfloat16 g_qkvh[(size_t)M_ * QKV_N];   // qkv hi (bf16)
__device__ __nv_bfloat16 g_qkvl[(size_t)M_ * QKV_N];   // qkv lo
__device__ __nv_bfloat16 g_ahi[(size_t)M_ * D_];       // attn out hi
__device__ __nv_bfloat16 g_alo[(size_t)M_ * D_];       // attn out lo
__device__ __nv_bfloat16 g_wqh[(size_t)QKV_N * D_];    // Wqkv^T [N,K]
__device__ __nv_bfloat16 g_wql[(size_t)QKV_N * D_];
__device__ __nv_bfloat16 g_wph[(size_t)D_ * D_];       // Wproj^T [N,K]
__device__ __nv_bfloat16 g_wpl[(size_t)D_ * D_];

// ---------------------------------------------------------------------------
// PTX helpers
// ---------------------------------------------------------------------------
__device__ __forceinline__ uint32_t smem_u32(const void* p) {
    uint32_t a;
    asm("{ .reg .u64 t; cvta.to.shared.u64 t, %1; cvt.u32.u64 %0, t; }"
        : "=r"(a) : "l"(p));
    return a;
}
__device__ __forceinline__ void cpasync16(uint32_t saddr, const void* g) {
    asm volatile("cp.async.cg.shared.global [%0], [%1], 16;" :: "r"(saddr), "l"(g));
}
#define CP_COMMIT() asm volatile("cp.async.commit_group;" ::: "memory")
#define CP_WAIT(n)  asm volatile("cp.async.wait_group %0;" :: "n"(n) : "memory")

__device__ __forceinline__ void ldm_x4(uint32_t* r, uint32_t addr) {
    asm volatile("ldmatrix.sync.aligned.m8n8.x4.shared.b16 {%0,%1,%2,%3}, [%4];"
                 : "=r"(r[0]), "=r"(r[1]), "=r"(r[2]), "=r"(r[3]) : "r"(addr));
}
__device__ __forceinline__ void ldm_x4_t(uint32_t* r, uint32_t addr) {
    asm volatile("ldmatrix.sync.aligned.m8n8.x4.trans.shared.b16 {%0,%1,%2,%3}, [%4];"
                 : "=r"(r[0]), "=r"(r[1]), "=r"(r[2]), "=r"(r[3]) : "r"(addr));
}
// not volatile: pure register op, ptxas may schedule freely
__device__ __forceinline__ void mma_bf16(float* c, const uint32_t* a,
                                         const uint32_t* b) {
    asm("mma.sync.aligned.m16n8k16.row.col.f32.bf16.bf16.f32 "
        "{%0,%1,%2,%3},{%4,%5,%6,%7},{%8,%9},{%0,%1,%2,%3};"
        : "+f"(c[0]), "+f"(c[1]), "+f"(c[2]), "+f"(c[3])
        : "r"(a[0]), "r"(a[1]), "r"(a[2]), "r"(a[3]), "r"(b[0]), "r"(b[1]));
}
// pack two fp32 into bf16x2 hi + residual lo
__device__ __forceinline__ void pack_hilo(float x, float y,
                                          uint32_t& hi, uint32_t& lo) {
    __nv_bfloat162 h2 = __floats2bfloat162_rn(x, y);
    float2 f2 = __bfloat1622float2(h2);
    __nv_bfloat162 l2 = __floats2bfloat162_rn(x - f2.x, y - f2.y);
    hi = *(uint32_t*)&h2;
    lo = *(uint32_t*)&l2;
}

// ---------------------------------------------------------------------------
// Split kernels
// ---------------------------------------------------------------------------
__global__ void split_a_kernel(const float* __restrict__ A,
                               __nv_bfloat16* __restrict__ Ah,
                               __nv_bfloat16* __restrict__ Al, int n4)
{
    int i = blockIdx.x * blockDim.x + threadIdx.x;
    if (i >= n4) return;
    float4 v = ((const float4*)A)[i];
    uint32_t h0, l0, h1, l1;
    pack_hilo(v.x, v.y, h0, l0);
    pack_hilo(v.z, v.w, h1, l1);
    ((uint32_t*)Ah)[2 * i]     = h0;
    ((uint32_t*)Ah)[2 * i + 1] = h1;
    ((uint32_t*)Al)[2 * i]     = l0;
    ((uint32_t*)Al)[2 * i + 1] = l1;
}

// W [K,N] fp32 -> Bh/Bl [N,K] bf16 (transpose + split)
__global__ void split_wT_kernel(const float* __restrict__ W,
                                __nv_bfloat16* __restrict__ Bh,
                                __nv_bfloat16* __restrict__ Bl, int K, int N)
{
    __shared__ float t[32][33];
    const int bx = blockIdx.x, by = blockIdx.y;
    const int tx = threadIdx.x, ty = threadIdx.y;
#pragma unroll
    for (int i = 0; i < 4; i++) {
        int k = by * 32 + ty + i * 8;
        t[ty + i * 8][tx] = W[(size_t)k * N + bx * 32 + tx];
    }
    __syncthreads();
#pragma unroll
    for (int i = 0; i < 4; i++) {
        int n = bx * 32 + ty + i * 8;
        int k = by * 32 + tx;
        float v = t[tx][ty + i * 8];
        __nv_bfloat16 h = __float2bfloat16_rn(v);
        Bh[(size_t)n * K + k] = h;
        Bl[(size_t)n * K + k] = __float2bfloat16_rn(v - __bfloat162float(h));
    }
}

// ---------------------------------------------------------------------------
// HMMA split-bf16 GEMM. SPLIT_OUT: write bf16 hi/lo instead of fp32.
// 2 CTAs/SM, 3-stage cp.async pipeline, ONE barrier per chunk.
// Hi tiles: pitch 80B (padded). Lo tiles: pitch 64B with 16B-chunk XOR swizzle
// (chunk ^= (row>>1)&3) -> conflict-free ldmatrix without padding.
// ---------------------------------------------------------------------------
constexpr int GBH = 128 * 80;              // 10240 per hi tile
constexpr int GBL = 128 * 64;              // 8192  per lo tile
constexpr int GSTAGE = 2 * GBH + 2 * GBL;  // 36864 (Ah,Bh,Al,Bl)
constexpr size_t GM_SMEM = 3 * GSTAGE;     // 110592 B

template <bool SPLIT_OUT>
__global__ void __launch_bounds__(256, 2) gemm_mma_kernel(
    const __nv_bfloat16* __restrict__ Ah, const __nv_bfloat16* __restrict__ Al,
    const __nv_bfloat16* __restrict__ Bh, const __nv_bfloat16* __restrict__ Bl,
    const float* __restrict__ bias, float* __restrict__ C,
    __nv_bfloat16* __restrict__ Ch, __nv_bfloat16* __restrict__ Cl,
    int N, int K)
{
    extern __shared__ char smem[];
    const uint32_t sb = smem_u32(smem);
    const int tid  = threadIdx.x;
    const int wid  = tid >> 5;
    const int lane = tid & 31;
    const int warp_m = wid >> 2;
    const int warp_n = wid & 3;
    const int row0 = blockIdx.y * 128;
    const int col0 = blockIdx.x * 128;

    float acc[4][4][4];
#pragma unroll
    for (int mt = 0; mt < 4; mt++)
#pragma unroll
        for (int nt = 0; nt < 4; nt++)
#pragma unroll
            for (int q = 0; q < 4; q++) acc[mt][nt][q] = 0.f;

    const int nChunks = K >> 5;
    const int lr0 = tid >> 2;          // 0..63
    const int lch = tid & 3;           // 16B chunk within 64B row

    auto load_stage = [&](int s, int c) {
        const int k0 = c << 5;
        const uint32_t st = sb + s * GSTAGE;
#pragma unroll
        for (int i = 0; i < 2; i++) {
            const int r = lr0 + i * 64;
            const uint32_t so_h = r * 80 + lch * 16;
            const uint32_t so_l = r * 64 + ((lch ^ ((r >> 1) & 3)) << 4);
            const size_t ga = (size_t)(row0 + r) * K + k0 + lch * 8;
            const size_t gb = (size_t)(col0 + r) * K + k0 + lch * 8;
            cpasync16(st + so_h, Ah + ga);
            cpasync16(st + GBH + so_h, Bh + gb);
            cpasync16(st + 2 * GBH + so_l, Al + ga);
            cpasync16(st + 2 * GBH + GBL + so_l, Bl + gb);
        }
    };

    load_stage(0, 0);
    CP_COMMIT();
    load_stage(1, 1);
    CP_COMMIT();

    const int arow  = warp_m * 64 + (lane & 15);
    const int acolb = ((lane >> 4) & 1) * 16;
    const int ahalf = (lane >> 4) & 1;
    const int bnrow = warp_n * 32 + (lane & 7) + ((lane >> 4) & 1) * 8;
    const int bcolb = ((lane >> 3) & 1) * 16;
    const int bhalf = (lane >> 3) & 1;

    int cur = 0, ldb = 2;
    for (int c = 0; c < nChunks; c++) {
        if (c + 1 < nChunks) { CP_WAIT(1); } else { CP_WAIT(0); }
        __syncthreads();                 // single barrier per chunk
        if (c + 2 < nChunks) {
            load_stage(ldb, c + 2);
            CP_COMMIT();
        }

        const uint32_t st  = sb + cur * GSTAGE;
        const uint32_t sAh = st;
        const uint32_t sBh = st + GBH;
        const uint32_t sAl = st + 2 * GBH;
        const uint32_t sBl = st + 2 * GBH + GBL;

#pragma unroll
        for (int ks = 0; ks < 2; ks++) {
            const int kb = ks * 32;
            // B fragments resident (hi + lo)
            uint32_t bh[4][2], bl[4][2];
#pragma unroll
            for (int np = 0; np < 2; np++) {
                const int rB = bnrow + np * 16;
                const uint32_t roh = (uint32_t)rB * 80 + bcolb + kb;
                const int cB = ks * 2 + bhalf;
                const uint32_t rol = (uint32_t)rB * 64 +
                                     ((cB ^ ((rB >> 1) & 3)) << 4);
                uint32_t t0[4], t1[4];
                ldm_x4(t0, sBh + roh);
                ldm_x4(t1, sBl + rol);
                bh[2 * np][0] = t0[0]; bh[2 * np][1] = t0[1];
                bh[2 * np + 1][0] = t0[2]; bh[2 * np + 1][1] = t0[3];
                bl[2 * np][0] = t1[0]; bl[2 * np][1] = t1[1];
                bl[2 * np + 1][0] = t1[2]; bl[2 * np + 1][1] = t1[3];
            }
            // A fragments streamed per mt (register-lean)
#pragma unroll
            for (int mt = 0; mt < 4; mt++) {
                const int rA = arow + mt * 16;
                const uint32_t roh = (uint32_t)rA * 80 + acolb + kb;
                const int cA = ks * 2 + ahalf;
                const uint32_t rol = (uint32_t)rA * 64 +
                                     ((cA ^ ((rA >> 1) & 3)) << 4);
                uint32_t ah[4], al[4];
                ldm_x4(ah, sAh + roh);
                ldm_x4(al, sAl + rol);
#pragma unroll
                for (int nt = 0; nt < 4; nt++)
                    mma_bf16(acc[mt][nt], ah, bh[nt]);
#pragma unroll
                for (int nt = 0; nt < 4; nt++)
                    mma_bf16(acc[mt][nt], ah, bl[nt]);
#pragma unroll
                for (int nt = 0; nt < 4; nt++)
                    mma_bf16(acc[mt][nt], al, bh[nt]);
            }
        }
        cur = (cur == 2) ? 0 : cur + 1;
        ldb = (ldb == 2) ? 0 : ldb + 1;
    }

    const int g  = lane >> 2;
    const int tc = (lane & 3) * 2;
#pragma unroll
    for (int nt = 0; nt < 4; nt++) {
        const int cg = col0 + warp_n * 32 + nt * 8 + tc;
        const float bx = bias[cg];
        const float by = bias[cg + 1];
#pragma unroll
        for (int mt = 0; mt < 4; mt++) {
            const int rg = row0 + warp_m * 64 + mt * 16 + g;
            float v00 = acc[mt][nt][0] + bx, v01 = acc[mt][nt][1] + by;
            float v10 = acc[mt][nt][2] + bx, v11 = acc[mt][nt][3] + by;
            if (SPLIT_OUT) {
                uint32_t h0, l0, h1, l1;
                pack_hilo(v00, v01, h0, l0);
                pack_hilo(v10, v11, h1, l1);
                *(uint32_t*)(Ch + (size_t)rg * N + cg)       = h0;
                *(uint32_t*)(Cl + (size_t)rg * N + cg)       = l0;
                *(uint32_t*)(Ch + (size_t)(rg + 8) * N + cg) = h1;
                *(uint32_t*)(Cl + (size_t)(rg + 8) * N + cg) = l1;
            } else {
                float2 a0; a0.x = v00; a0.y = v01;
                float2 a1; a1.x = v10; a1.y = v11;
                *(float2*)(C + (size_t)rg * N + cg)       = a0;
                *(float2*)(C + (size_t)(rg + 8) * N + cg) = a1;
            }
        }
    }
}

// ---------------------------------------------------------------------------
// Tensor-core flash attention (causal). CTA = 128 q-rows x (b,h). 8 warps.
// 3-stage K/V cp.async pipeline, ONE barrier per key-tile.
// S = QhKh+QhKl+QlKh ; PV = PhVh+PhVl+PlVh ; fp32 accum throughout.
// ---------------------------------------------------------------------------
constexpr int APB      = 144;               // smem pitch bytes (72 bf16)
constexpr int AT_QB    = 128 * APB;         // 18432 per Q tensor
constexpr int AT_KVT   = 64 * APB;          // 9216 per K/V tensor tile
constexpr int AT_STAGE = 4 * AT_KVT;        // 36864
constexpr size_t AT_SMEM = 2 * (size_t)AT_QB + 3 * (size_t)AT_STAGE;  // 147456

__global__ void __launch_bounds__(256, 1) attn_mma_kernel(
    const __nv_bfloat16* __restrict__ qkvh,
    const __nv_bfloat16* __restrict__ qkvl,
    __nv_bfloat16* __restrict__ outh,
    __nv_bfloat16* __restrict__ outl)
{
    extern __shared__ char smem[];
    const uint32_t sb = smem_u32(smem);
    const uint32_t sQh = sb;
    const uint32_t sQl = sb + AT_QB;
    const uint32_t sS0 = sb + 2 * AT_QB;

    const int qb = blockIdx.x;              // q-tile (128 rows)
    const int h  = blockIdx.y;
    const int b  = blockIdx.z;
    const int tid  = threadIdx.x;
    const int wid  = tid >> 5;
    const int lane = tid & 31;

    const size_t qrow0 = (size_t)(b * L_ + qb * 128);

    // ---- Q hi/lo -> smem (group 0) ----
#pragma unroll
    for (int i = 0; i < 4; i++) {
        const int id = i * 256 + tid;
        const int r = id >> 3, s = id & 7;
        const size_t g = (qrow0 + r) * QKV_N + h * HD_ + s * 8;
        const uint32_t so = r * APB + s * 16;
        cpasync16(sQh + so, qkvh + g);
        cpasync16(sQl + so, qkvl + g);
    }
    CP_COMMIT();

    const int nkt = 2 * qb + 2;             // >= 2 always

    auto load_kv = [&](int buf, int kt) {
        const uint32_t st = sS0 + buf * AT_STAGE;
        const size_t krow0 = (size_t)(b * L_ + kt * 64);
#pragma unroll
        for (int i = 0; i < 2; i++) {
            const int id = i * 256 + tid;
            const int r = id >> 3, s = id & 7;
            const size_t gk = (krow0 + r) * QKV_N + D_ + h * HD_ + s * 8;
            const size_t gv = gk + D_;
            const uint32_t so = r * APB + s * 16;
            cpasync16(st + 0 * AT_KVT + so, qkvh + gk);
            cpasync16(st + 1 * AT_KVT + so, qkvl + gk);
            cpasync16(st + 2 * AT_KVT + so, qkvh + gv);
            cpasync16(st + 3 * AT_KVT + so, qkvl + gv);
        }
    };

    load_kv(0, 0);
    CP_COMMIT();
    load_kv(1, 1);
    CP_COMMIT();

    // ---- Q fragments (Q group done after WAIT(2)) ----
    CP_WAIT(2);
    __syncthreads();
    uint32_t qh[4][4], ql[4][4];
    {
        const uint32_t base = (uint32_t)(wid * 16 + (lane & 15)) * APB +
                              ((lane >> 4) & 1) * 16;
#pragma unroll
        for (int j = 0; j < 4; j++) {
            ldm_x4(qh[j], sQh + base + j * 32);
            ldm_x4(ql[j], sQl + base + j * 32);
        }
    }

    float o[8][4];
#pragma unroll
    for (int nt = 0; nt < 8; nt++)
#pragma unroll
        for (int q = 0; q < 4; q++) o[nt][q] = 0.f;
    float m0 = -CUDART_INF_F, m1 = -CUDART_INF_F;
    float l0 = 0.f, l1 = 0.f;

    const int row_r0 = qb * 128 + wid * 16 + (lane >> 2);  // global q row (and +8)
    const int ccol   = 2 * (lane & 3);
    constexpr float SCALE = 0.125f;
    constexpr float LOG2E = 1.44269504f;

    int cur = 0, ldb = 2;
    for (int kt = 0; kt < nkt; kt++) {
        if (kt + 1 < nkt) { CP_WAIT(1); } else { CP_WAIT(0); }
        __syncthreads();                 // single barrier per key tile
        if (kt + 2 < nkt) {
            load_kv(ldb, kt + 2);
            CP_COMMIT();
        }

        const uint32_t st  = sS0 + cur * AT_STAGE;
        const uint32_t sKh = st;
        const uint32_t sKl = st + AT_KVT;
        const uint32_t sVh = st + 2 * AT_KVT;
        const uint32_t sVl = st + 3 * AT_KVT;

        // ---- S = Q K^T (3 split passes) ----
        float s[8][4];
#pragma unroll
        for (int nt = 0; nt < 8; nt++)
#pragma unroll
            for (int q = 0; q < 4; q++) s[nt][q] = 0.f;

        const uint32_t kbase = (uint32_t)((lane & 7) + ((lane >> 4) & 1) * 8) * APB +
                               ((lane >> 3) & 1) * 16;
#pragma unroll
        for (int j = 0; j < 4; j++) {
            uint32_t kh[8][2], kl[8][2];
#pragma unroll
            for (int np = 0; np < 4; np++) {
                const uint32_t ro = kbase + (uint32_t)(np * 16) * APB + j * 32;
                uint32_t t0[4], t1[4];
                ldm_x4(t0, sKh + ro);
                ldm_x4(t1, sKl + ro);
                kh[2 * np][0] = t0[0]; kh[2 * np][1] = t0[1];
                kh[2 * np + 1][0] = t0[2]; kh[2 * np + 1][1] = t0[3];
                kl[2 * np][0] = t1[0]; kl[2 * np][1] = t1[1];
                kl[2 * np + 1][0] = t1[2]; kl[2 * np + 1][1] = t1[3];
            }
#pragma unroll
            for (int nt = 0; nt < 8; nt++)
                mma_bf16(s[nt], qh[j], kh[nt]);
#pragma unroll
            for (int nt = 0; nt < 8; nt++)
                mma_bf16(s[nt], qh[j], kl[nt]);
#pragma unroll
            for (int nt = 0; nt < 8; nt++)
                mma_bf16(s[nt], ql[j], kh[nt]);
        }

        // ---- scale + causal mask ----
#pragma unroll
        for (int nt = 0; nt < 8; nt++)
#pragma unroll
            for (int q = 0; q < 4; q++) s[nt][q] *= SCALE;

        if (kt >= 2 * qb) {
#pragma unroll
            for (int nt = 0; nt < 8; nt++) {
                const int col = kt * 64 + nt * 8 + ccol;
                if (col > row_r0)         s[nt][0] = -CUDART_INF_F;
                if (col + 1 > row_r0)     s[nt][1] = -CUDART_INF_F;
                if (col > row_r0 + 8)     s[nt][2] = -CUDART_INF_F;
                if (col + 1 > row_r0 + 8) s[nt][3] = -CUDART_INF_F;
            }
        }

        // ---- online softmax ----
        float tm0 = -CUDART_INF_F, tm1 = -CUDART_INF_F;
#pragma unroll
        for (int nt = 0; nt < 8; nt++) {
            tm0 = fmaxf(tm0, fmaxf(s[nt][0], s[nt][1]));
            tm1 = fmaxf(tm1, fmaxf(s[nt][2], s[nt][3]));
        }
        tm0 = fmaxf(tm0, __shfl_xor_sync(0xffffffffu, tm0, 1));
        tm0 = fmaxf(tm0, __shfl_xor_sync(0xffffffffu, tm0, 2));
        tm1 = fmaxf(tm1, __shfl_xor_sync(0xffffffffu, tm1, 1));
        tm1 = fmaxf(tm1, __shfl_xor_sync(0xffffffffu, tm1, 2));

        const float mn0 = fmaxf(m0, tm0);
        const float mn1 = fmaxf(m1, tm1);
        const float a0 = exp2f((m0 - mn0) * LOG2E);
        const float a1 = exp2f((m1 - mn1) * LOG2E);
        m0 = mn0; m1 = mn1;

        float rs0 = 0.f, rs1 = 0.f;
#pragma unroll
        for (int nt = 0; nt < 8; nt++) {
            float p0 = exp2f((s[nt][0] - mn0) * LOG2E);
            float p1 = exp2f((s[nt][1] - mn0) * LOG2E);
            float p2 = exp2f((s[nt][2] - mn1) * LOG2E);
            float p3 = exp2f((s[nt][3] - mn1) * LOG2E);
            s[nt][0] = p0; s[nt][1] = p1; s[nt][2] = p2; s[nt][3] = p3;
            rs0 += p0 + p1;
            rs1 += p2 + p3;
        }
        rs0 += __shfl_xor_sync(0xffffffffu, rs0, 1);
        rs0 += __shfl_xor_sync(0xffffffffu, rs0, 2);
        rs1 += __shfl_xor_sync(0xffffffffu, rs1, 1);
        rs1 += __shfl_xor_sync(0xffffffffu, rs1, 2);
        l0 = a0 * l0 + rs0;
        l1 = a1 * l1 + rs1;

#pragma unroll
        for (int nt = 0; nt < 8; nt++) {
            o[nt][0] *= a0; o[nt][1] *= a0;
            o[nt][2] *= a1; o[nt][3] *= a1;
        }

        // ---- pack P (C-frag -> A-frag identity) ----
        uint32_t ph[4][4], pl[4][4];
#pragma unroll
        for (int j = 0; j < 4; j++) {
            pack_hilo(s[2 * j][0],     s[2 * j][1],     ph[j][0], pl[j][0]);
            pack_hilo(s[2 * j][2],     s[2 * j][3],     ph[j][1], pl[j][1]);
            pack_hilo(s[2 * j + 1][0], s[2 * j + 1][1], ph[j][2], pl[j][2]);
            pack_hilo(s[2 * j + 1][2], s[2 * j + 1][3], ph[j][3], pl[j][3]);
        }

        // ---- O += P V (3 split passes); V via ldmatrix.trans ----
        const int vmat = lane >> 3;
        const uint32_t vrowb = (uint32_t)((vmat & 1) * 8 + (lane & 7)) * APB +
                               (vmat >> 1) * 16;
#pragma unroll
        for (int j = 0; j < 4; j++) {
            uint32_t vh[8][2], vl[8][2];
#pragma unroll
            for (int pp = 0; pp < 4; pp++) {
                const uint32_t ro = vrowb + (uint32_t)(j * 16) * APB + pp * 32;
                uint32_t t0[4], t1[4];
                ldm_x4_t(t0, sVh + ro);
                ldm_x4_t(t1, sVl + ro);
                vh[2 * pp][0] = t0[0]; vh[2 * pp][1] = t0[1];
                vh[2 * pp + 1][0] = t0[2]; vh[2 * pp + 1][1] = t0[3];
                vl[2 * pp][0] = t1[0]; vl[2 * pp][1] = t1[1];
                vl[2 * pp + 1][0] = t1[2]; vl[2 * pp + 1][1] = t1[3];
            }
#pragma unroll
            for (int nt = 0; nt < 8; nt++)
                mma_bf16(o[nt], ph[j], vh[nt]);
#pragma unroll
            for (int nt = 0; nt < 8; nt++)
                mma_bf16(o[nt], ph[j], vl[nt]);
#pragma unroll
            for (int nt = 0; nt < 8; nt++)
                mma_bf16(o[nt], pl[j], vh[nt]);
        }
        cur = (cur == 2) ? 0 : cur + 1;
        ldb = (ldb == 2) ? 0 : ldb + 1;
    }

    // ---- finalize: /l, split hi/lo, store ----
    const float inv0 = 1.0f / l0;
    const float inv1 = 1.0f / l1;
    const size_t grow0 = qrow0 + wid * 16 + (lane >> 2);
#pragma unroll
    for (int nt = 0; nt < 8; nt++) {
        const int col = h * HD_ + nt * 8 + ccol;
        uint32_t h0, lo0, h1, lo1;
        pack_hilo(o[nt][0] * inv0, o[nt][1] * inv0, h0, lo0);
        pack_hilo(o[nt][2] * inv1, o[nt][3] * inv1, h1, lo1);
        *(uint32_t*)(outh + grow0 * D_ + col)       = h0;
        *(uint32_t*)(outl + grow0 * D_ + col)       = lo0;
        *(uint32_t*)(outh + (grow0 + 8) * D_ + col) = h1;
        *(uint32_t*)(outl + (grow0 + 8) * D_ + col) = lo1;
    }
}

// ----------------------------------------------------------------------------
// Launch
// ----------------------------------------------------------------------------
extern "C" void kernel_launch(void* const* d_in, const int* in_sizes, int n_in,
                              void* d_out, int out_size)
{
    const float* x     = (const float*)d_in[0];
    const float* Wqkv  = (const float*)d_in[1];
    const float* bqkv  = (const float*)d_in[2];
    const float* Wproj = (const float*)d_in[3];
    const float* bproj = (const float*)d_in[4];
    float* out = (float*)d_out;

    __nv_bfloat16 *xhi, *xlo, *qkvh, *qkvl, *ahi, *alo, *wqh, *wql, *wph, *wpl;
    cudaGetSymbolAddress((void**)&xhi, g_xhi);
    cudaGetSymbolAddress((void**)&xlo, g_xlo);
    cudaGetSymbolAddress((void**)&qkvh, g_qkvh);
    cudaGetSymbolAddress((void**)&qkvl, g_qkvl);
    cudaGetSymbolAddress((void**)&ahi, g_ahi);
    cudaGetSymbolAddress((void**)&alo, g_alo);
    cudaGetSymbolAddress((void**)&wqh, g_wqh);
    cudaGetSymbolAddress((void**)&wql, g_wql);
    cudaGetSymbolAddress((void**)&wph, g_wph);
    cudaGetSymbolAddress((void**)&wpl, g_wpl);

    static bool attr_set = false;
    if (!attr_set) {
        cudaFuncSetAttribute(gemm_mma_kernel<true>,
                             cudaFuncAttributeMaxDynamicSharedMemorySize,
                             (int)GM_SMEM);
        cudaFuncSetAttribute(gemm_mma_kernel<false>,
                             cudaFuncAttributeMaxDynamicSharedMemorySize,
                             (int)GM_SMEM);
        cudaFuncSetAttribute(attn_mma_kernel,
                             cudaFuncAttributeMaxDynamicSharedMemorySize,
                             (int)AT_SMEM);
        attr_set = true;
    }

    const int n4x = M_ * D_ / 4;

    // prep: splits
    split_a_kernel<<<(n4x + 255) / 256, 256>>>(x, xhi, xlo, n4x);
    split_wT_kernel<<<dim3(QKV_N / 32, D_ / 32), dim3(32, 8)>>>(Wqkv, wqh, wql, D_, QKV_N);
    split_wT_kernel<<<dim3(D_ / 32, D_ / 32), dim3(32, 8)>>>(Wproj, wph, wpl, D_, D_);

    // 1) QKV projection -> bf16 hi/lo directly
    gemm_mma_kernel<true><<<dim3(QKV_N / 128, M_ / 128), 256, GM_SMEM>>>(
        xhi, xlo, wqh, wql, bqkv, nullptr, qkvh, qkvl, QKV_N, D_);

    // 2) causal flash attention (tensor cores) -> bf16 hi/lo
    attn_mma_kernel<<<dim3(L_ / 128, H_, B_), 256, AT_SMEM>>>(qkvh, qkvl, ahi, alo);

    // 3) output projection -> fp32 out
    gemm_mma_kernel<false><<<dim3(D_ / 128, M_ / 128), 256, GM_SMEM>>>(
        ahi, alo, wph, wpl, bproj, out, nullptr, nullptr, D_, D_);
}

// round 10
// speedup vs baseline: 3.1012x; 1.0498x over previous
#include <cuda_runtime.h>
#include <cuda_bf16.h>
#include <math_constants.h>
#include <cstdint>

// Problem constants
constexpr int B_  = 4;
constexpr int L_  = 2048;
constexpr int D_  = 1024;
constexpr int H_  = 16;
constexpr int HD_ = 64;
constexpr int M_  = B_ * L_;       // 8192
constexpr int QKV_N = 3 * D_;      // 3072

// ---------------------------------------------------------------------------
// Scratch (allocation-free -> __device__ globals)
// ---------------------------------------------------------------------------
__device__ __nv_bfloat16 g_xhi[(size_t)M_ * D_];
__device__ __nv_bfloat16 g_xlo[(size_t)M_ * D_];
__device__ __nv_bfloat16 g_qkvh[(size_t)M_ * QKV_N];   // qkv hi (bf16)
__device__ __nv_bfloat16 g_qkvl[(size_t)M_ * QKV_N];   // qkv lo
__device__ __nv_bfloat16 g_ahi[(size_t)M_ * D_];       // attn out hi
__device__ __nv_bfloat16 g_alo[(size_t)M_ * D_];       // attn out lo
__device__ __nv_bfloat16 g_wqh[(size_t)QKV_N * D_];    // Wqkv^T [N,K]
__device__ __nv_bfloat16 g_wql[(size_t)QKV_N * D_];
__device__ __nv_bfloat16 g_wph[(size_t)D_ * D_];       // Wproj^T [N,K]
__device__ __nv_bfloat16 g_wpl[(size_t)D_ * D_];

// ---------------------------------------------------------------------------
// PTX helpers
// ---------------------------------------------------------------------------
__device__ __forceinline__ uint32_t smem_u32(const void* p) {
    uint32_t a;
    asm("{ .reg .u64 t; cvta.to.shared.u64 t, %1; cvt.u32.u64 %0, t; }"
        : "=r"(a) : "l"(p));
    return a;
}
__device__ __forceinline__ void cpasync16(uint32_t saddr, const void* g) {
    asm volatile("cp.async.cg.shared.global [%0], [%1], 16;" :: "r"(saddr), "l"(g));
}
#define CP_COMMIT() asm volatile("cp.async.commit_group;" ::: "memory")
#define CP_WAIT(n)  asm volatile("cp.async.wait_group %0;" :: "n"(n) : "memory")

__device__ __forceinline__ void ldm_x4(uint32_t* r, uint32_t addr) {
    asm volatile("ldmatrix.sync.aligned.m8n8.x4.shared.b16 {%0,%1,%2,%3}, [%4];"
                 : "=r"(r[0]), "=r"(r[1]), "=r"(r[2]), "=r"(r[3]) : "r"(addr));
}
__device__ __forceinline__ void ldm_x4_t(uint32_t* r, uint32_t addr) {
    asm volatile("ldmatrix.sync.aligned.m8n8.x4.trans.shared.b16 {%0,%1,%2,%3}, [%4];"
                 : "=r"(r[0]), "=r"(r[1]), "=r"(r[2]), "=r"(r[3]) : "r"(addr));
}
// not volatile: pure register op, ptxas may schedule freely
__device__ __forceinline__ void mma_bf16(float* c, const uint32_t* a,
                                         const uint32_t* b) {
    asm("mma.sync.aligned.m16n8k16.row.col.f32.bf16.bf16.f32 "
        "{%0,%1,%2,%3},{%4,%5,%6,%7},{%8,%9},{%0,%1,%2,%3};"
        : "+f"(c[0]), "+f"(c[1]), "+f"(c[2]), "+f"(c[3])
        : "r"(a[0]), "r"(a[1]), "r"(a[2]), "r"(a[3]), "r"(b[0]), "r"(b[1]));
}
// pack two fp32 into bf16x2 hi + residual lo
__device__ __forceinline__ void pack_hilo(float x, float y,
                                          uint32_t& hi, uint32_t& lo) {
    __nv_bfloat162 h2 = __floats2bfloat162_rn(x, y);
    float2 f2 = __bfloat1622float2(h2);
    __nv_bfloat162 l2 = __floats2bfloat162_rn(x - f2.x, y - f2.y);
    hi = *(uint32_t*)&h2;
    lo = *(uint32_t*)&l2;
}

// ---------------------------------------------------------------------------
// Split kernels
// ---------------------------------------------------------------------------
__global__ void split_a_kernel(const float* __restrict__ A,
                               __nv_bfloat16* __restrict__ Ah,
                               __nv_bfloat16* __restrict__ Al, int n4)
{
    int i = blockIdx.x * blockDim.x + threadIdx.x;
    if (i >= n4) return;
    float4 v = ((const float4*)A)[i];
    uint32_t h0, l0, h1, l1;
    pack_hilo(v.x, v.y, h0, l0);
    pack_hilo(v.z, v.w, h1, l1);
    ((uint32_t*)Ah)[2 * i]     = h0;
    ((uint32_t*)Ah)[2 * i + 1] = h1;
    ((uint32_t*)Al)[2 * i]     = l0;
    ((uint32_t*)Al)[2 * i + 1] = l1;
}

// W [K,N] fp32 -> Bh/Bl [N,K] bf16 (transpose + split)
__global__ void split_wT_kernel(const float* __restrict__ W,
                                __nv_bfloat16* __restrict__ Bh,
                                __nv_bfloat16* __restrict__ Bl, int K, int N)
{
    __shared__ float t[32][33];
    const int bx = blockIdx.x, by = blockIdx.y;
    const int tx = threadIdx.x, ty = threadIdx.y;
#pragma unroll
    for (int i = 0; i < 4; i++) {
        int k = by * 32 + ty + i * 8;
        t[ty + i * 8][tx] = W[(size_t)k * N + bx * 32 + tx];
    }
    __syncthreads();
#pragma unroll
    for (int i = 0; i < 4; i++) {
        int n = bx * 32 + ty + i * 8;
        int k = by * 32 + tx;
        float v = t[tx][ty + i * 8];
        __nv_bfloat16 h = __float2bfloat16_rn(v);
        Bh[(size_t)n * K + k] = h;
        Bl[(size_t)n * K + k] = __float2bfloat16_rn(v - __bfloat162float(h));
    }
}

// ---------------------------------------------------------------------------
// HMMA split-bf16 GEMM. SPLIT_OUT: write bf16 hi/lo instead of fp32.
// 2 CTAs/SM, 3-stage cp.async pipeline, ONE barrier per chunk.
// Intra-warp software pipeline: A-fragments double-buffered across the 8
// (ks,mt) slots; the 8 cp.async issues for chunk c+2 spread 1-per-slot.
// Hi tiles: pitch 80B. Lo tiles: pitch 64B + 16B-chunk XOR swizzle.
// ---------------------------------------------------------------------------
constexpr int GBH = 128 * 80;              // 10240 per hi tile
constexpr int GBL = 128 * 64;              // 8192  per lo tile
constexpr int GSTAGE = 2 * GBH + 2 * GBL;  // 36864 (Ah,Bh,Al,Bl)
constexpr size_t GM_SMEM = 3 * GSTAGE;     // 110592 B

template <bool SPLIT_OUT>
__global__ void __launch_bounds__(256, 2) gemm_mma_kernel(
    const __nv_bfloat16* __restrict__ Ah, const __nv_bfloat16* __restrict__ Al,
    const __nv_bfloat16* __restrict__ Bh, const __nv_bfloat16* __restrict__ Bl,
    const float* __restrict__ bias, float* __restrict__ C,
    __nv_bfloat16* __restrict__ Ch, __nv_bfloat16* __restrict__ Cl,
    int N, int K)
{
    extern __shared__ char smem[];
    const uint32_t sb = smem_u32(smem);
    const int tid  = threadIdx.x;
    const int wid  = tid >> 5;
    const int lane = tid & 31;
    const int warp_m = wid >> 2;
    const int warp_n = wid & 3;
    const int row0 = blockIdx.y * 128;
    const int col0 = blockIdx.x * 128;

    float acc[4][4][4];
#pragma unroll
    for (int mt = 0; mt < 4; mt++)
#pragma unroll
        for (int nt = 0; nt < 4; nt++)
#pragma unroll
            for (int q = 0; q < 4; q++) acc[mt][nt][q] = 0.f;

    const int nChunks = K >> 5;
    const int lr0 = tid >> 2;          // 0..63
    const int lch = tid & 3;           // 16B chunk within 64B row

    // full-stage load (prologue only)
    auto load_stage = [&](int s, int c) {
        const int k0 = c << 5;
        const uint32_t st = sb + s * GSTAGE;
#pragma unroll
        for (int i = 0; i < 2; i++) {
            const int r = lr0 + i * 64;
            const uint32_t so_h = r * 80 + lch * 16;
            const uint32_t so_l = r * 64 + ((lch ^ ((r >> 1) & 3)) << 4);
            const size_t ga = (size_t)(row0 + r) * K + k0 + lch * 8;
            const size_t gb = (size_t)(col0 + r) * K + k0 + lch * 8;
            cpasync16(st + so_h, Ah + ga);
            cpasync16(st + GBH + so_h, Bh + gb);
            cpasync16(st + 2 * GBH + so_l, Al + ga);
            cpasync16(st + 2 * GBH + GBL + so_l, Bl + gb);
        }
    };
    // one of 8 per-thread loads (spread through the compute slots)
    auto load_slot = [&](int s, int c2, int slot) {
        const int k0 = c2 << 5;
        const uint32_t st = sb + s * GSTAGE;
        const int i = slot >> 2;
        const int which = slot & 3;
        const int r = lr0 + i * 64;
        const uint32_t so_h = r * 80 + lch * 16;
        const uint32_t so_l = r * 64 + ((lch ^ ((r >> 1) & 3)) << 4);
        if (which == 0)
            cpasync16(st + so_h, Ah + (size_t)(row0 + r) * K + k0 + lch * 8);
        else if (which == 1)
            cpasync16(st + GBH + so_h, Bh + (size_t)(col0 + r) * K + k0 + lch * 8);
        else if (which == 2)
            cpasync16(st + 2 * GBH + so_l, Al + (size_t)(row0 + r) * K + k0 + lch * 8);
        else
            cpasync16(st + 2 * GBH + GBL + so_l,
                      Bl + (size_t)(col0 + r) * K + k0 + lch * 8);
    };

    load_stage(0, 0);
    CP_COMMIT();
    load_stage(1, 1);
    CP_COMMIT();

    const int arow  = warp_m * 64 + (lane & 15);
    const int acolb = ((lane >> 4) & 1) * 16;
    const int ahalf = (lane >> 4) & 1;
    const int bnrow = warp_n * 32 + (lane & 7) + ((lane >> 4) & 1) * 8;
    const int bcolb = ((lane >> 3) & 1) * 16;
    const int bhalf = (lane >> 3) & 1;

    int cur = 0, ldb = 2;
    for (int c = 0; c < nChunks; c++) {
        if (c + 1 < nChunks) { CP_WAIT(1); } else { CP_WAIT(0); }
        __syncthreads();                 // single barrier per chunk
        const bool doLoad = (c + 2 < nChunks);

        const uint32_t st  = sb + cur * GSTAGE;
        const uint32_t sAh = st;
        const uint32_t sBh = st + GBH;
        const uint32_t sAl = st + 2 * GBH;
        const uint32_t sBl = st + 2 * GBH + GBL;

        auto ldA = [&](uint32_t* h, uint32_t* l, int ks, int mt) {
            const int rA = arow + mt * 16;
            const uint32_t roh = (uint32_t)rA * 80 + acolb + ks * 32;
            const int cA = ks * 2 + ahalf;
            const uint32_t rol = (uint32_t)rA * 64 +
                                 ((cA ^ ((rA >> 1) & 3)) << 4);
            ldm_x4(h, sAh + roh);
            ldm_x4(l, sAl + rol);
        };

        uint32_t aH[2][4], aL[2][4];
        ldA(aH[0], aL[0], 0, 0);         // preload first slot

#pragma unroll
        for (int ks = 0; ks < 2; ks++) {
            const int kb = ks * 32;
            // B fragments resident for this k16 step (hi + lo)
            uint32_t bh[4][2], bl[4][2];
#pragma unroll
            for (int np = 0; np < 2; np++) {
                const int rB = bnrow + np * 16;
                const uint32_t roh = (uint32_t)rB * 80 + bcolb + kb;
                const int cB = ks * 2 + bhalf;
                const uint32_t rol = (uint32_t)rB * 64 +
                                     ((cB ^ ((rB >> 1) & 3)) << 4);
                uint32_t t0[4], t1[4];
                ldm_x4(t0, sBh + roh);
                ldm_x4(t1, sBl + rol);
                bh[2 * np][0] = t0[0]; bh[2 * np][1] = t0[1];
                bh[2 * np + 1][0] = t0[2]; bh[2 * np + 1][1] = t0[3];
                bl[2 * np][0] = t1[0]; bl[2 * np][1] = t1[1];
                bl[2 * np + 1][0] = t1[2]; bl[2 * np + 1][1] = t1[3];
            }
#pragma unroll
            for (int mt = 0; mt < 4; mt++) {
                const int slot = ks * 4 + mt;
                // spread one cp.async per slot (next-next chunk)
                if (doLoad) load_slot(ldb, c + 2, slot);
                // prefetch next slot's A fragments (hidden under MMAs)
                if (slot < 7) {
                    const int ns = slot + 1;
                    ldA(aH[ns & 1], aL[ns & 1], ns >> 2, ns & 3);
                }
                const uint32_t* ah = aH[slot & 1];
                const uint32_t* al = aL[slot & 1];
#pragma unroll
                for (int nt = 0; nt < 4; nt++)
                    mma_bf16(acc[mt][nt], ah, bh[nt]);
#pragma unroll
                for (int nt = 0; nt < 4; nt++)
                    mma_bf16(acc[mt][nt], ah, bl[nt]);
#pragma unroll
                for (int nt = 0; nt < 4; nt++)
                    mma_bf16(acc[mt][nt], al, bh[nt]);
            }
        }
        if (doLoad) CP_COMMIT();
        cur = (cur == 2) ? 0 : cur + 1;
        ldb = (ldb == 2) ? 0 : ldb + 1;
    }

    const int g  = lane >> 2;
    const int tc = (lane & 3) * 2;
#pragma unroll
    for (int nt = 0; nt < 4; nt++) {
        const int cg = col0 + warp_n * 32 + nt * 8 + tc;
        const float bx = bias[cg];
        const float by = bias[cg + 1];
#pragma unroll
        for (int mt = 0; mt < 4; mt++) {
            const int rg = row0 + warp_m * 64 + mt * 16 + g;
            float v00 = acc[mt][nt][0] + bx, v01 = acc[mt][nt][1] + by;
            float v10 = acc[mt][nt][2] + bx, v11 = acc[mt][nt][3] + by;
            if (SPLIT_OUT) {
                uint32_t h0, l0, h1, l1;
                pack_hilo(v00, v01, h0, l0);
                pack_hilo(v10, v11, h1, l1);
                *(uint32_t*)(Ch + (size_t)rg * N + cg)       = h0;
                *(uint32_t*)(Cl + (size_t)rg * N + cg)       = l0;
                *(uint32_t*)(Ch + (size_t)(rg + 8) * N + cg) = h1;
                *(uint32_t*)(Cl + (size_t)(rg + 8) * N + cg) = l1;
            } else {
                float2 a0; a0.x = v00; a0.y = v01;
                float2 a1; a1.x = v10; a1.y = v11;
                *(float2*)(C + (size_t)rg * N + cg)       = a0;
                *(float2*)(C + (size_t)(rg + 8) * N + cg) = a1;
            }
        }
    }
}

// ---------------------------------------------------------------------------
// Tensor-core flash attention (causal). CTA = 128 q-rows x (b,h). 8 warps.
// 3-stage K/V cp.async pipeline, ONE barrier per key-tile. (unchanged R9)
// ---------------------------------------------------------------------------
constexpr int APB      = 144;               // smem pitch bytes (72 bf16)
constexpr int AT_QB    = 128 * APB;         // 18432 per Q tensor
constexpr int AT_KVT   = 64 * APB;          // 9216 per K/V tensor tile
constexpr int AT_STAGE = 4 * AT_KVT;        // 36864
constexpr size_t AT_SMEM = 2 * (size_t)AT_QB + 3 * (size_t)AT_STAGE;  // 147456

__global__ void __launch_bounds__(256, 1) attn_mma_kernel(
    const __nv_bfloat16* __restrict__ qkvh,
    const __nv_bfloat16* __restrict__ qkvl,
    __nv_bfloat16* __restrict__ outh,
    __nv_bfloat16* __restrict__ outl)
{
    extern __shared__ char smem[];
    const uint32_t sb = smem_u32(smem);
    const uint32_t sQh = sb;
    const uint32_t sQl = sb + AT_QB;
    const uint32_t sS0 = sb + 2 * AT_QB;

    const int qb = blockIdx.x;              // q-tile (128 rows)
    const int h  = blockIdx.y;
    const int b  = blockIdx.z;
    const int tid  = threadIdx.x;
    const int wid  = tid >> 5;
    const int lane = tid & 31;

    const size_t qrow0 = (size_t)(b * L_ + qb * 128);

    // ---- Q hi/lo -> smem (group 0) ----
#pragma unroll
    for (int i = 0; i < 4; i++) {
        const int id = i * 256 + tid;
        const int r = id >> 3, s = id & 7;
        const size_t g = (qrow0 + r) * QKV_N + h * HD_ + s * 8;
        const uint32_t so = r * APB + s * 16;
        cpasync16(sQh + so, qkvh + g);
        cpasync16(sQl + so, qkvl + g);
    }
    CP_COMMIT();

    const int nkt = 2 * qb + 2;             // >= 2 always

    auto load_kv = [&](int buf, int kt) {
        const uint32_t st = sS0 + buf * AT_STAGE;
        const size_t krow0 = (size_t)(b * L_ + kt * 64);
#pragma unroll
        for (int i = 0; i < 2; i++) {
            const int id = i * 256 + tid;
            const int r = id >> 3, s = id & 7;
            const size_t gk = (krow0 + r) * QKV_N + D_ + h * HD_ + s * 8;
            const size_t gv = gk + D_;
            const uint32_t so = r * APB + s * 16;
            cpasync16(st + 0 * AT_KVT + so, qkvh + gk);
            cpasync16(st + 1 * AT_KVT + so, qkvl + gk);
            cpasync16(st + 2 * AT_KVT + so, qkvh + gv);
            cpasync16(st + 3 * AT_KVT + so, qkvl + gv);
        }
    };

    load_kv(0, 0);
    CP_COMMIT();
    load_kv(1, 1);
    CP_COMMIT();

    // ---- Q fragments (Q group done after WAIT(2)) ----
    CP_WAIT(2);
    __syncthreads();
    uint32_t qh[4][4], ql[4][4];
    {
        const uint32_t base = (uint32_t)(wid * 16 + (lane & 15)) * APB +
                              ((lane >> 4) & 1) * 16;
#pragma unroll
        for (int j = 0; j < 4; j++) {
            ldm_x4(qh[j], sQh + base + j * 32);
            ldm_x4(ql[j], sQl + base + j * 32);
        }
    }

    float o[8][4];
#pragma unroll
    for (int nt = 0; nt < 8; nt++)
#pragma unroll
        for (int q = 0; q < 4; q++) o[nt][q] = 0.f;
    float m0 = -CUDART_INF_F, m1 = -CUDART_INF_F;
    float l0 = 0.f, l1 = 0.f;

    const int row_r0 = qb * 128 + wid * 16 + (lane >> 2);  // global q row (and +8)
    const int ccol   = 2 * (lane & 3);
    constexpr float SCALE = 0.125f;
    constexpr float LOG2E = 1.44269504f;

    int cur = 0, ldb = 2;
    for (int kt = 0; kt < nkt; kt++) {
        if (kt + 1 < nkt) { CP_WAIT(1); } else { CP_WAIT(0); }
        __syncthreads();                 // single barrier per key tile
        if (kt + 2 < nkt) {
            load_kv(ldb, kt + 2);
            CP_COMMIT();
        }

        const uint32_t st  = sS0 + cur * AT_STAGE;
        const uint32_t sKh = st;
        const uint32_t sKl = st + AT_KVT;
        const uint32_t sVh = st + 2 * AT_KVT;
        const uint32_t sVl = st + 3 * AT_KVT;

        // ---- S = Q K^T (3 split passes) ----
        float s[8][4];
#pragma unroll
        for (int nt = 0; nt < 8; nt++)
#pragma unroll
            for (int q = 0; q < 4; q++) s[nt][q] = 0.f;

        const uint32_t kbase = (uint32_t)((lane & 7) + ((lane >> 4) & 1) * 8) * APB +
                               ((lane >> 3) & 1) * 16;
#pragma unroll
        for (int j = 0; j < 4; j++) {
            uint32_t kh[8][2], kl[8][2];
#pragma unroll
            for (int np = 0; np < 4; np++) {
                const uint32_t ro = kbase + (uint32_t)(np * 16) * APB + j * 32;
                uint32_t t0[4], t1[4];
                ldm_x4(t0, sKh + ro);
                ldm_x4(t1, sKl + ro);
                kh[2 * np][0] = t0[0]; kh[2 * np][1] = t0[1];
                kh[2 * np + 1][0] = t0[2]; kh[2 * np + 1][1] = t0[3];
                kl[2 * np][0] = t1[0]; kl[2 * np][1] = t1[1];
                kl[2 * np + 1][0] = t1[2]; kl[2 * np + 1][1] = t1[3];
            }
#pragma unroll
            for (int nt = 0; nt < 8; nt++)
                mma_bf16(s[nt], qh[j], kh[nt]);
#pragma unroll
            for (int nt = 0; nt < 8; nt++)
                mma_bf16(s[nt], qh[j], kl[nt]);
#pragma unroll
            for (int nt = 0; nt < 8; nt++)
                mma_bf16(s[nt], ql[j], kh[nt]);
        }

        // ---- scale + causal mask ----
#pragma unroll
        for (int nt = 0; nt < 8; nt++)
#pragma unroll
            for (int q = 0; q < 4; q++) s[nt][q] *= SCALE;

        if (kt >= 2 * qb) {
#pragma unroll
            for (int nt = 0; nt < 8; nt++) {
                const int col = kt * 64 + nt * 8 + ccol;
                if (col > row_r0)         s[nt][0] = -CUDART_INF_F;
                if (col + 1 > row_r0)     s[nt][1] = -CUDART_INF_F;
                if (col > row_r0 + 8)     s[nt][2] = -CUDART_INF_F;
                if (col + 1 > row_r0 + 8) s[nt][3] = -CUDART_INF_F;
            }
        }

        // ---- online softmax ----
        float tm0 = -CUDART_INF_F, tm1 = -CUDART_INF_F;
#pragma unroll
        for (int nt = 0; nt < 8; nt++) {
            tm0 = fmaxf(tm0, fmaxf(s[nt][0], s[nt][1]));
            tm1 = fmaxf(tm1, fmaxf(s[nt][2], s[nt][3]));
        }
        tm0 = fmaxf(tm0, __shfl_xor_sync(0xffffffffu, tm0, 1));
        tm0 = fmaxf(tm0, __shfl_xor_sync(0xffffffffu, tm0, 2));
        tm1 = fmaxf(tm1, __shfl_xor_sync(0xffffffffu, tm1, 1));
        tm1 = fmaxf(tm1, __shfl_xor_sync(0xffffffffu, tm1, 2));

        const float mn0 = fmaxf(m0, tm0);
        const float mn1 = fmaxf(m1, tm1);
        const float a0 = exp2f((m0 - mn0) * LOG2E);
        const float a1 = exp2f((m1 - mn1) * LOG2E);
        m0 = mn0; m1 = mn1;

        float rs0 = 0.f, rs1 = 0.f;
#pragma unroll
        for (int nt = 0; nt < 8; nt++) {
            float p0 = exp2f((s[nt][0] - mn0) * LOG2E);
            float p1 = exp2f((s[nt][1] - mn0) * LOG2E);
            float p2 = exp2f((s[nt][2] - mn1) * LOG2E);
            float p3 = exp2f((s[nt][3] - mn1) * LOG2E);
            s[nt][0] = p0; s[nt][1] = p1; s[nt][2] = p2; s[nt][3] = p3;
            rs0 += p0 + p1;
            rs1 += p2 + p3;
        }
        rs0 += __shfl_xor_sync(0xffffffffu, rs0, 1);
        rs0 += __shfl_xor_sync(0xffffffffu, rs0, 2);
        rs1 += __shfl_xor_sync(0xffffffffu, rs1, 1);
        rs1 += __shfl_xor_sync(0xffffffffu, rs1, 2);
        l0 = a0 * l0 + rs0;
        l1 = a1 * l1 + rs1;

#pragma unroll
        for (int nt = 0; nt < 8; nt++) {
            o[nt][0] *= a0; o[nt][1] *= a0;
            o[nt][2] *= a1; o[nt][3] *= a1;
        }

        // ---- pack P (C-frag -> A-frag identity) ----
        uint32_t ph[4][4], pl[4][4];
#pragma unroll
        for (int j = 0; j < 4; j++) {
            pack_hilo(s[2 * j][0],     s[2 * j][1],     ph[j][0], pl[j][0]);
            pack_hilo(s[2 * j][2],     s[2 * j][3],     ph[j][1], pl[j][1]);
            pack_hilo(s[2 * j + 1][0], s[2 * j + 1][1], ph[j][2], pl[j][2]);
            pack_hilo(s[2 * j + 1][2], s[2 * j + 1][3], ph[j][3], pl[j][3]);
        }

        // ---- O += P V (3 split passes); V via ldmatrix.trans ----
        const int vmat = lane >> 3;
        const uint32_t vrowb = (uint32_t)((vmat & 1) * 8 + (lane & 7)) * APB +
                               (vmat >> 1) * 16;
#pragma unroll
        for (int j = 0; j < 4; j++) {
            uint32_t vh[8][2], vl[8][2];
#pragma unroll
            for (int pp = 0; pp < 4; pp++) {
                const uint32_t ro = vrowb + (uint32_t)(j * 16) * APB + pp * 32;
                uint32_t t0[4], t1[4];
                ldm_x4_t(t0, sVh + ro);
                ldm_x4_t(t1, sVl + ro);
                vh[2 * pp][0] = t0[0]; vh[2 * pp][1] = t0[1];
                vh[2 * pp + 1][0] = t0[2]; vh[2 * pp + 1][1] = t0[3];
                vl[2 * pp][0] = t1[0]; vl[2 * pp][1] = t1[1];
                vl[2 * pp + 1][0] = t1[2]; vl[2 * pp + 1][1] = t1[3];
            }
#pragma unroll
            for (int nt = 0; nt < 8; nt++)
                mma_bf16(o[nt], ph[j], vh[nt]);
#pragma unroll
            for (int nt = 0; nt < 8; nt++)
                mma_bf16(o[nt], ph[j], vl[nt]);
#pragma unroll
            for (int nt = 0; nt < 8; nt++)
                mma_bf16(o[nt], pl[j], vh[nt]);
        }
        cur = (cur == 2) ? 0 : cur + 1;
        ldb = (ldb == 2) ? 0 : ldb + 1;
    }

    // ---- finalize: /l, split hi/lo, store ----
    const float inv0 = 1.0f / l0;
    const float inv1 = 1.0f / l1;
    const size_t grow0 = qrow0 + wid * 16 + (lane >> 2);
#pragma unroll
    for (int nt = 0; nt < 8; nt++) {
        const int col = h * HD_ + nt * 8 + ccol;
        uint32_t h0, lo0, h1, lo1;
        pack_hilo(o[nt][0] * inv0, o[nt][1] * inv0, h0, lo0);
        pack_hilo(o[nt][2] * inv1, o[nt][3] * inv1, h1, lo1);
        *(uint32_t*)(outh + grow0 * D_ + col)       = h0;
        *(uint32_t*)(outl + grow0 * D_ + col)       = lo0;
        *(uint32_t*)(outh + (grow0 + 8) * D_ + col) = h1;
        *(uint32_t*)(outl + (grow0 + 8) * D_ + col) = lo1;
    }
}

// ----------------------------------------------------------------------------
// Launch
// ----------------------------------------------------------------------------
extern "C" void kernel_launch(void* const* d_in, const int* in_sizes, int n_in,
                              void* d_out, int out_size)
{
    const float* x     = (const float*)d_in[0];
    const float* Wqkv  = (const float*)d_in[1];
    const float* bqkv  = (const float*)d_in[2];
    const float* Wproj = (const float*)d_in[3];
    const float* bproj = (const float*)d_in[4];
    float* out = (float*)d_out;

    __nv_bfloat16 *xhi, *xlo, *qkvh, *qkvl, *ahi, *alo, *wqh, *wql, *wph, *wpl;
    cudaGetSymbolAddress((void**)&xhi, g_xhi);
    cudaGetSymbolAddress((void**)&xlo, g_xlo);
    cudaGetSymbolAddress((void**)&qkvh, g_qkvh);
    cudaGetSymbolAddress((void**)&qkvl, g_qkvl);
    cudaGetSymbolAddress((void**)&ahi, g_ahi);
    cudaGetSymbolAddress((void**)&alo, g_alo);
    cudaGetSymbolAddress((void**)&wqh, g_wqh);
    cudaGetSymbolAddress((void**)&wql, g_wql);
    cudaGetSymbolAddress((void**)&wph, g_wph);
    cudaGetSymbolAddress((void**)&wpl, g_wpl);

    static bool attr_set = false;
    if (!attr_set) {
        cudaFuncSetAttribute(gemm_mma_kernel<true>,
                             cudaFuncAttributeMaxDynamicSharedMemorySize,
                             (int)GM_SMEM);
        cudaFuncSetAttribute(gemm_mma_kernel<false>,
                             cudaFuncAttributeMaxDynamicSharedMemorySize,
                             (int)GM_SMEM);
        cudaFuncSetAttribute(attn_mma_kernel,
                             cudaFuncAttributeMaxDynamicSharedMemorySize,
                             (int)AT_SMEM);
        attr_set = true;
    }

    const int n4x = M_ * D_ / 4;

    // prep: splits
    split_a_kernel<<<(n4x + 255) / 256, 256>>>(x, xhi, xlo, n4x);
    split_wT_kernel<<<dim3(QKV_N / 32, D_ / 32), dim3(32, 8)>>>(Wqkv, wqh, wql, D_, QKV_N);
    split_wT_kernel<<<dim3(D_ / 32, D_ / 32), dim3(32, 8)>>>(Wproj, wph, wpl, D_, D_);

    // 1) QKV projection -> bf16 hi/lo directly
    gemm_mma_kernel<true><<<dim3(QKV_N / 128, M_ / 128), 256, GM_SMEM>>>(
        xhi, xlo, wqh, wql, bqkv, nullptr, qkvh, qkvl, QKV_N, D_);

    // 2) causal flash attention (tensor cores) -> bf16 hi/lo
    attn_mma_kernel<<<dim3(L_ / 128, H_, B_), 256, AT_SMEM>>>(qkvh, qkvl, ahi, alo);

    // 3) output projection -> fp32 out
    gemm_mma_kernel<false><<<dim3(D_ / 128, M_ / 128), 256, GM_SMEM>>>(
        ahi, alo, wph, wpl, bproj, out, nullptr, nullptr, D_, D_);
}